// round 1
// baseline (speedup 1.0000x reference)
#include <cuda_runtime.h>
#include <math.h>

// Problem constants
#define Bc 4
#define Sc 64
#define Nc 256
#define Fc 32
#define Hc 64
#define Mc (Bc*Sc)     // 256 graphs
#define Rc (Bc*Nc)     // 1024 sequences
#define Tc Sc          // 64 timesteps
#define G4c (4*Hc)     // 256 gate columns
#define NEGV (-9e15f)

// ---------------- device scratch (no allocations allowed) ----------------
__device__ float d_h[Mc*Nc*Hc];          // GAT projected features (current layer)
__device__ float d_g[Mc*Nc*Hc];          // GAT layer output
__device__ float d_si[Mc*Nc];
__device__ float d_sj[Mc*Nc];
__device__ float d_seq[Rc*Tc*Hc];        // LSTM input sequences [r][t][h]
__device__ float d_xg[2*Rc*Tc*G4c];      // precomputed input gates [dir][r][tau][k]
__device__ float d_hs0[2*Rc*Tc*Hc];      // layer0 hidden outputs (scan order)
__device__ float d_hlast[2*Rc*Hc];       // layer1 final hidden per dir

__device__ __forceinline__ float warp_sum(float v){
    #pragma unroll
    for (int o=16;o;o>>=1) v += __shfl_xor_sync(0xffffffffu, v, o);
    return v;
}
__device__ __forceinline__ float warp_max(float v){
    #pragma unroll
    for (int o=16;o;o>>=1) v = fmaxf(v, __shfl_xor_sync(0xffffffffu, v, o));
    return v;
}
__device__ __forceinline__ float sigf(float x){ return 1.f/(1.f+__expf(-x)); }

// ---------------- GAT projection: h = X @ W, s_i = h.a1, s_j = h.a2 ------
template<int FIN_, bool FROM_G>
__global__ void __launch_bounds__(64) k_proj(const float* __restrict__ X,
    const float* __restrict__ W, const float* __restrict__ a)
{
    int row = blockIdx.x;           // m*Nc + n
    int h = threadIdx.x;            // 0..63
    __shared__ float xr[FIN_];
    __shared__ float red[4];
    const float* src = FROM_G ? d_g : X;
    if (h < FIN_) xr[h] = src[row*FIN_ + h];
    __syncthreads();
    float acc = 0.f;
    #pragma unroll
    for (int f = 0; f < FIN_; ++f) acc += xr[f] * W[f*Hc + h];
    d_h[row*Hc + h] = acc;
    float v1 = warp_sum(acc * a[h]);
    float v2 = warp_sum(acc * a[Hc + h]);
    if ((h & 31) == 0){ red[h>>5] = v1; red[2 + (h>>5)] = v2; }
    __syncthreads();
    if (h == 0){ d_si[row] = red[0] + red[1]; d_sj[row] = red[2] + red[3]; }
}

// --------- GAT attention + aggregation + LayerNorm + ELU  ----------------
// One block = (graph m, 32 consecutive destination rows i). Thread t owns
// output column h = t&63 within source chunk c = t>>6, keeping the 64
// corresponding h-tile values in registers for the whole block.
__global__ void __launch_bounds__(256) k_attn(const float* __restrict__ adj,
    const float* __restrict__ gamma, const float* __restrict__ beta)
{
    const int m  = blockIdx.x >> 3;
    const int i0 = (blockIdx.x & 7) * 32;
    const int t  = threadIdx.x;
    const int h  = t & 63, c = t >> 6;

    __shared__ float p[Nc];
    __shared__ float red[8];
    __shared__ float part[256];
    __shared__ float hrow[64];
    __shared__ float lnred[4];

    float hreg[64];
    const float* Hb = d_h + (m*Nc + c*64)*Hc + h;
    #pragma unroll
    for (int j = 0; j < 64; ++j) hreg[j] = Hb[j*Hc];

    const float sjv = d_sj[m*Nc + t];
    const float* adjm = adj + (size_t)(m*Nc + i0)*Nc;

    for (int ii = 0; ii < 32; ++ii){
        const int i = i0 + ii;
        float e = d_si[m*Nc + i] + sjv;
        e = e > 0.f ? e : 0.2f*e;
        if (adjm[ii*Nc + t] <= 0.f) e = NEGV;

        // block max
        float w = warp_max(e);
        if ((t & 31) == 0) red[t>>5] = w;
        __syncthreads();
        float mx = fmaxf(fmaxf(fmaxf(red[0],red[1]),fmaxf(red[2],red[3])),
                         fmaxf(fmaxf(red[4],red[5]),fmaxf(red[6],red[7])));
        float pe = __expf(e - mx);
        float sw = warp_sum(pe);
        __syncthreads();
        if ((t & 31) == 0) red[t>>5] = sw;
        __syncthreads();
        float denom = red[0]+red[1]+red[2]+red[3]+red[4]+red[5]+red[6]+red[7];
        p[t] = pe / denom;
        __syncthreads();

        // aggregation: hp[h] = sum_j att[j] * h[j][h]
        float acc = 0.f;
        const float4* pc = (const float4*)&p[c*64];
        #pragma unroll
        for (int j4 = 0; j4 < 16; ++j4){
            float4 pv = pc[j4];
            acc += pv.x*hreg[j4*4+0] + pv.y*hreg[j4*4+1]
                 + pv.z*hreg[j4*4+2] + pv.w*hreg[j4*4+3];
        }
        part[t] = acc;
        __syncthreads();
        if (t < 64) hrow[t] = part[t] + part[t+64] + part[t+128] + part[t+192];
        __syncthreads();

        // LayerNorm + ELU over the 64-wide row
        if (t < 64){
            float v = hrow[t];
            float s1 = warp_sum(v);
            float s2 = warp_sum(v*v);
            if ((t & 31) == 0){ lnred[t>>5] = s1; lnred[2 + (t>>5)] = s2; }
        }
        __syncthreads();
        if (t < 64){
            float mean = (lnred[0]+lnred[1]) * (1.f/64.f);
            float var  = (lnred[2]+lnred[3]) * (1.f/64.f) - mean*mean;
            float hn = (hrow[t]-mean)*rsqrtf(var + 1e-5f)*gamma[t] + beta[t];
            d_g[(m*Nc + i)*Hc + t] = hn > 0.f ? hn : expm1f(hn);
        }
        __syncthreads();
    }
}

// ------- residual + gated combine + [B,S,N,H]->[B*N,S,H] transpose -------
__global__ void __launch_bounds__(64) k_comb(const float* __restrict__ X,
    const float* __restrict__ Wr, const float* __restrict__ br,
    const float* __restrict__ alpha)
{
    int row = blockIdx.x;           // m*Nc + n
    int m = row >> 8, n = row & 255;
    int b = m / Sc, s = m % Sc;
    int h = threadIdx.x;
    __shared__ float xr[Fc];
    if (h < Fc) xr[h] = X[row*Fc + h];
    __syncthreads();
    float acc = br[h];
    #pragma unroll
    for (int f = 0; f < Fc; ++f) acc += xr[f] * Wr[f*Hc + h];
    float gate = fminf(fmaxf(alpha[0], 0.f), 1.f);
    d_seq[((b*Nc + n)*Tc + s)*Hc + h] = acc + gate * d_g[row*Hc + h];
}

// ---------- LSTM input-gate precompute: xg = in @ Wih + bih + bhh --------
// One block = (dir, sequence r, 4 consecutive scan steps). Thread k owns one
// gate column; 4 timesteps share each weight load.
template<int IN_, bool L1>
__global__ void __launch_bounds__(256) k_xg(const float* __restrict__ Wih,
    const float* __restrict__ bih, const float* __restrict__ bhh)
{
    int dir = blockIdx.y;
    int r   = blockIdx.x >> 4;
    int tg  = blockIdx.x & 15;
    int k   = threadIdx.x;
    __shared__ float rowsT[IN_][4];   // [h][tau-in-group]

    #pragma unroll
    for (int q = 0; q < 4; ++q){
        int tau = tg*4 + q;
        int tt = dir ? (Tc-1-tau) : tau;      // time consumed at this scan step
        if (!L1){
            if (k < IN_) rowsT[k][q] = d_seq[(r*Tc + tt)*Hc + k];
        } else {
            if (k < 64)       rowsT[k][q] = d_hs0[((0*Rc + r)*Tc + tt)*Hc + k];
            else if (k < 128) rowsT[k][q] = d_hs0[((1*Rc + r)*Tc + (Tc-1-tt))*Hc + (k-64)];
        }
    }
    __syncthreads();

    const float* Wd = Wih + dir*IN_*G4c;
    float bv = bih[dir*G4c + k] + bhh[dir*G4c + k];
    float acc0 = bv, acc1 = bv, acc2 = bv, acc3 = bv;
    #pragma unroll
    for (int hh = 0; hh < IN_; ++hh){
        float4 rv = *(const float4*)&rowsT[hh][0];
        float wv = Wd[hh*G4c + k];
        acc0 += rv.x*wv; acc1 += rv.y*wv; acc2 += rv.z*wv; acc3 += rv.w*wv;
    }
    int base = ((dir*Rc + r)*Tc + tg*4)*G4c + k;
    d_xg[base]         = acc0;
    d_xg[base +   G4c] = acc1;
    d_xg[base + 2*G4c] = acc2;
    d_xg[base + 3*G4c] = acc3;
}

// ------------------------- LSTM recurrence -------------------------------
// One block = (dir, 8 sequences). Thread k keeps Whh[:,k] in 64 registers;
// hidden state broadcast from smem as float2. Cell state lives in registers
// (thread owns hidden unit k&63 of rows k>>6 and 4+(k>>6)).
template<bool L1>
__global__ void __launch_bounds__(256) k_rec(const float* __restrict__ Whh)
{
    int dir = blockIdx.y;
    int r0  = blockIdx.x * 8;
    int k   = threadIdx.x;
    __shared__ float hsm[8][Hc];
    __shared__ float gsm[8][G4c];

    float w[Hc];
    const float* Wd = Whh + dir*Hc*G4c;
    #pragma unroll
    for (int hh = 0; hh < Hc; ++hh) w[hh] = Wd[hh*G4c + k];

    for (int idx = k; idx < 8*Hc; idx += 256) hsm[idx>>6][idx&63] = 0.f;
    float cc0 = 0.f, cc1 = 0.f;
    const int hid = k & 63, rA = k >> 6, rB = 4 + (k >> 6);
    __syncthreads();

    const float* xgd = d_xg + (size_t)dir * Rc * Tc * G4c;
    for (int tau = 0; tau < Tc; ++tau){
        #pragma unroll
        for (int row = 0; row < 8; ++row){
            float acc = xgd[((r0+row)*Tc + tau)*G4c + k];
            #pragma unroll
            for (int hh = 0; hh < Hc; hh += 2){
                float2 hv = *(const float2*)&hsm[row][hh];
                acc += hv.x*w[hh] + hv.y*w[hh+1];
            }
            gsm[row][k] = acc;
        }
        __syncthreads();
        {
            float gi = gsm[rA][hid],      gf = gsm[rA][64+hid];
            float gg = gsm[rA][128+hid],  go = gsm[rA][192+hid];
            float cn = sigf(gf)*cc0 + sigf(gi)*tanhf(gg);
            float hn = sigf(go)*tanhf(cn);
            cc0 = cn; hsm[rA][hid] = hn;
            if (!L1) d_hs0[((dir*Rc + r0 + rA)*Tc + tau)*Hc + hid] = hn;
        }
        {
            float gi = gsm[rB][hid],      gf = gsm[rB][64+hid];
            float gg = gsm[rB][128+hid],  go = gsm[rB][192+hid];
            float cn = sigf(gf)*cc1 + sigf(gi)*tanhf(gg);
            float hn = sigf(go)*tanhf(cn);
            cc1 = cn; hsm[rB][hid] = hn;
            if (!L1) d_hs0[((dir*Rc + r0 + rB)*Tc + tau)*Hc + hid] = hn;
        }
        __syncthreads();
    }
    if (L1){
        d_hlast[(dir*Rc + r0 + rA)*Hc + hid] = hsm[rA][hid];
        d_hlast[(dir*Rc + r0 + rB)*Hc + hid] = hsm[rB][hid];
    }
}

// --------------------------- final FC ------------------------------------
__global__ void __launch_bounds__(128) k_fc(const float* __restrict__ fcW,
    const float* __restrict__ fcb, float* __restrict__ out)
{
    int r = blockIdx.x * blockDim.x + threadIdx.x;
    if (r >= Rc) return;
    float acc = fcb[0];
    #pragma unroll
    for (int hh = 0; hh < Hc; ++hh) acc += d_hlast[r*Hc + hh]       * fcW[hh];
    #pragma unroll
    for (int hh = 0; hh < Hc; ++hh) acc += d_hlast[(Rc + r)*Hc + hh] * fcW[64 + hh];
    out[r] = acc;
}

// --------------------------------------------------------------------------
extern "C" void kernel_launch(void* const* d_in, const int* in_sizes, int n_in,
                              void* d_out, int out_size)
{
    const float* x       = (const float*)d_in[0];
    const float* adj     = (const float*)d_in[1];
    const float* gat0_W  = (const float*)d_in[2];
    const float* gat0_a  = (const float*)d_in[3];
    const float* gat0_g  = (const float*)d_in[4];
    const float* gat0_b  = (const float*)d_in[5];
    const float* gat1_W  = (const float*)d_in[6];
    const float* gat1_a  = (const float*)d_in[7];
    const float* gat1_g  = (const float*)d_in[8];
    const float* gat1_b  = (const float*)d_in[9];
    const float* res_W   = (const float*)d_in[10];
    const float* res_b   = (const float*)d_in[11];
    const float* alpha   = (const float*)d_in[12];
    const float* l0_Wih  = (const float*)d_in[13];
    const float* l0_Whh  = (const float*)d_in[14];
    const float* l0_bih  = (const float*)d_in[15];
    const float* l0_bhh  = (const float*)d_in[16];
    const float* l1_Wih  = (const float*)d_in[17];
    const float* l1_Whh  = (const float*)d_in[18];
    const float* l1_bih  = (const float*)d_in[19];
    const float* l1_bhh  = (const float*)d_in[20];
    const float* fc_W    = (const float*)d_in[21];
    const float* fc_b    = (const float*)d_in[22];
    float* out = (float*)d_out;

    // GAT layer 0
    k_proj<Fc, false><<<Mc*Nc, 64>>>(x, gat0_W, gat0_a);
    k_attn<<<Mc*8, 256>>>(adj, gat0_g, gat0_b);
    // GAT layer 1
    k_proj<Hc, true><<<Mc*Nc, 64>>>(nullptr, gat1_W, gat1_a);
    k_attn<<<Mc*8, 256>>>(adj, gat1_g, gat1_b);
    // residual combine + transpose to sequences
    k_comb<<<Mc*Nc, 64>>>(x, res_W, res_b, alpha);
    // BiLSTM layer 0
    k_xg<Hc, false><<<dim3(Rc*16, 2), 256>>>(l0_Wih, l0_bih, l0_bhh);
    k_rec<false><<<dim3(Rc/8, 2), 256>>>(l0_Whh);
    // BiLSTM layer 1
    k_xg<2*Hc, true><<<dim3(Rc*16, 2), 256>>>(l1_Wih, l1_bih, l1_bhh);
    k_rec<true><<<dim3(Rc/8, 2), 256>>>(l1_Whh);
    // final FC
    k_fc<<<(Rc + 127)/128, 128>>>(fc_W, fc_b, out);
}

// round 2
// speedup vs baseline: 1.0004x; 1.0004x over previous
#include <cuda_runtime.h>
#include <math.h>

// Problem constants
#define Bc 4
#define Sc 64
#define Nc 256
#define Fc 32
#define Hc 64
#define Mc (Bc*Sc)     // 256 graphs
#define Rc (Bc*Nc)     // 1024 sequences
#define Tc Sc          // 64 timesteps
#define G4c (4*Hc)     // 256 gate columns
#define NEGV (-9e15f)

// ---------------- device scratch (no allocations allowed) ----------------
__device__ float d_h[Mc*Nc*Hc];          // GAT projected features (current layer)
__device__ float d_g[Mc*Nc*Hc];          // GAT layer output
__device__ float d_si[Mc*Nc];
__device__ float d_sj[Mc*Nc];
__device__ float d_seq[Rc*Tc*Hc];        // LSTM input sequences [r][t][h]
__device__ float d_xg[2*Rc*Tc*G4c];      // precomputed input gates [dir][r][tau][k]
__device__ float d_hs0[2*Rc*Tc*Hc];      // layer0 hidden outputs (scan order)
__device__ float d_hlast[2*Rc*Hc];       // layer1 final hidden per dir

__device__ __forceinline__ float warp_sum(float v){
    #pragma unroll
    for (int o=16;o;o>>=1) v += __shfl_xor_sync(0xffffffffu, v, o);
    return v;
}
__device__ __forceinline__ float warp_max(float v){
    #pragma unroll
    for (int o=16;o;o>>=1) v = fmaxf(v, __shfl_xor_sync(0xffffffffu, v, o));
    return v;
}
__device__ __forceinline__ float sigf(float x){ return 1.f/(1.f+__expf(-x)); }

// ---------------- GAT projection: h = X @ W, s_i = h.a1, s_j = h.a2 ------
template<int FIN_, bool FROM_G>
__global__ void __launch_bounds__(64) k_proj(const float* __restrict__ X,
    const float* __restrict__ W, const float* __restrict__ a)
{
    int row = blockIdx.x;           // m*Nc + n
    int h = threadIdx.x;            // 0..63
    __shared__ float xr[FIN_];
    __shared__ float red[4];
    const float* src = FROM_G ? d_g : X;
    if (h < FIN_) xr[h] = src[row*FIN_ + h];
    __syncthreads();
    float acc = 0.f;
    #pragma unroll
    for (int f = 0; f < FIN_; ++f) acc += xr[f] * W[f*Hc + h];
    d_h[row*Hc + h] = acc;
    float v1 = warp_sum(acc * a[h]);
    float v2 = warp_sum(acc * a[Hc + h]);
    if ((h & 31) == 0){ red[h>>5] = v1; red[2 + (h>>5)] = v2; }
    __syncthreads();
    if (h == 0){ d_si[row] = red[0] + red[1]; d_sj[row] = red[2] + red[3]; }
}

// --------- GAT attention + aggregation + LayerNorm + ELU  ----------------
// One block = (graph m, 32 consecutive destination rows i). Thread t owns
// output column h = t&63 within source chunk c = t>>6, keeping the 64
// corresponding h-tile values in registers for the whole block.
__global__ void __launch_bounds__(256) k_attn(const float* __restrict__ adj,
    const float* __restrict__ gamma, const float* __restrict__ beta)
{
    const int m  = blockIdx.x >> 3;
    const int i0 = (blockIdx.x & 7) * 32;
    const int t  = threadIdx.x;
    const int h  = t & 63, c = t >> 6;

    __shared__ float p[Nc];
    __shared__ float red[8];
    __shared__ float part[256];
    __shared__ float hrow[64];
    __shared__ float lnred[4];

    float hreg[64];
    const float* Hb = d_h + (m*Nc + c*64)*Hc + h;
    #pragma unroll
    for (int j = 0; j < 64; ++j) hreg[j] = Hb[j*Hc];

    const float sjv = d_sj[m*Nc + t];
    const float* adjm = adj + (size_t)(m*Nc + i0)*Nc;

    for (int ii = 0; ii < 32; ++ii){
        const int i = i0 + ii;
        float e = d_si[m*Nc + i] + sjv;
        e = e > 0.f ? e : 0.2f*e;
        if (adjm[ii*Nc + t] <= 0.f) e = NEGV;

        // block max
        float w = warp_max(e);
        if ((t & 31) == 0) red[t>>5] = w;
        __syncthreads();
        float mx = fmaxf(fmaxf(fmaxf(red[0],red[1]),fmaxf(red[2],red[3])),
                         fmaxf(fmaxf(red[4],red[5]),fmaxf(red[6],red[7])));
        float pe = __expf(e - mx);
        float sw = warp_sum(pe);
        __syncthreads();
        if ((t & 31) == 0) red[t>>5] = sw;
        __syncthreads();
        float denom = red[0]+red[1]+red[2]+red[3]+red[4]+red[5]+red[6]+red[7];
        p[t] = pe / denom;
        __syncthreads();

        // aggregation: hp[h] = sum_j att[j] * h[j][h]
        float acc = 0.f;
        const float4* pc = (const float4*)&p[c*64];
        #pragma unroll
        for (int j4 = 0; j4 < 16; ++j4){
            float4 pv = pc[j4];
            acc += pv.x*hreg[j4*4+0] + pv.y*hreg[j4*4+1]
                 + pv.z*hreg[j4*4+2] + pv.w*hreg[j4*4+3];
        }
        part[t] = acc;
        __syncthreads();
        if (t < 64) hrow[t] = part[t] + part[t+64] + part[t+128] + part[t+192];
        __syncthreads();

        // LayerNorm + ELU over the 64-wide row
        if (t < 64){
            float v = hrow[t];
            float s1 = warp_sum(v);
            float s2 = warp_sum(v*v);
            if ((t & 31) == 0){ lnred[t>>5] = s1; lnred[2 + (t>>5)] = s2; }
        }
        __syncthreads();
        if (t < 64){
            float mean = (lnred[0]+lnred[1]) * (1.f/64.f);
            float var  = (lnred[2]+lnred[3]) * (1.f/64.f) - mean*mean;
            float hn = (hrow[t]-mean)*rsqrtf(var + 1e-5f)*gamma[t] + beta[t];
            d_g[(m*Nc + i)*Hc + t] = hn > 0.f ? hn : expm1f(hn);
        }
        __syncthreads();
    }
}

// ------- residual + gated combine + [B,S,N,H]->[B*N,S,H] transpose -------
__global__ void __launch_bounds__(64) k_comb(const float* __restrict__ X,
    const float* __restrict__ Wr, const float* __restrict__ br,
    const float* __restrict__ alpha)
{
    int row = blockIdx.x;           // m*Nc + n
    int m = row >> 8, n = row & 255;
    int b = m / Sc, s = m % Sc;
    int h = threadIdx.x;
    __shared__ float xr[Fc];
    if (h < Fc) xr[h] = X[row*Fc + h];
    __syncthreads();
    float acc = br[h];
    #pragma unroll
    for (int f = 0; f < Fc; ++f) acc += xr[f] * Wr[f*Hc + h];
    float gate = fminf(fmaxf(alpha[0], 0.f), 1.f);
    d_seq[((b*Nc + n)*Tc + s)*Hc + h] = acc + gate * d_g[row*Hc + h];
}

// ---------- LSTM input-gate precompute: xg = in @ Wih + bih + bhh --------
// One block = (dir, sequence r, 4 consecutive scan steps). Thread k owns one
// gate column; 4 timesteps share each weight load.
template<int IN_, bool L1>
__global__ void __launch_bounds__(256) k_xg(const float* __restrict__ Wih,
    const float* __restrict__ bih, const float* __restrict__ bhh)
{
    int dir = blockIdx.y;
    int r   = blockIdx.x >> 4;
    int tg  = blockIdx.x & 15;
    int k   = threadIdx.x;
    __shared__ float rowsT[IN_][4];   // [h][tau-in-group]

    #pragma unroll
    for (int q = 0; q < 4; ++q){
        int tau = tg*4 + q;
        int tt = dir ? (Tc-1-tau) : tau;      // time consumed at this scan step
        if (!L1){
            if (k < IN_) rowsT[k][q] = d_seq[(r*Tc + tt)*Hc + k];
        } else {
            if (k < 64)       rowsT[k][q] = d_hs0[((0*Rc + r)*Tc + tt)*Hc + k];
            else if (k < 128) rowsT[k][q] = d_hs0[((1*Rc + r)*Tc + (Tc-1-tt))*Hc + (k-64)];
        }
    }
    __syncthreads();

    const float* Wd = Wih + dir*IN_*G4c;
    float bv = bih[dir*G4c + k] + bhh[dir*G4c + k];
    float acc0 = bv, acc1 = bv, acc2 = bv, acc3 = bv;
    #pragma unroll
    for (int hh = 0; hh < IN_; ++hh){
        float4 rv = *(const float4*)&rowsT[hh][0];
        float wv = Wd[hh*G4c + k];
        acc0 += rv.x*wv; acc1 += rv.y*wv; acc2 += rv.z*wv; acc3 += rv.w*wv;
    }
    int base = ((dir*Rc + r)*Tc + tg*4)*G4c + k;
    d_xg[base]         = acc0;
    d_xg[base +   G4c] = acc1;
    d_xg[base + 2*G4c] = acc2;
    d_xg[base + 3*G4c] = acc3;
}

// ------------------------- LSTM recurrence -------------------------------
// One block = (dir, 8 sequences). Thread k keeps Whh[:,k] in 64 registers;
// hidden state broadcast from smem as float2. Cell state lives in registers
// (thread owns hidden unit k&63 of rows k>>6 and 4+(k>>6)).
template<bool L1>
__global__ void __launch_bounds__(256) k_rec(const float* __restrict__ Whh)
{
    int dir = blockIdx.y;
    int r0  = blockIdx.x * 8;
    int k   = threadIdx.x;
    __shared__ float hsm[8][Hc];
    __shared__ float gsm[8][G4c];

    float w[Hc];
    const float* Wd = Whh + dir*Hc*G4c;
    #pragma unroll
    for (int hh = 0; hh < Hc; ++hh) w[hh] = Wd[hh*G4c + k];

    for (int idx = k; idx < 8*Hc; idx += 256) hsm[idx>>6][idx&63] = 0.f;
    float cc0 = 0.f, cc1 = 0.f;
    const int hid = k & 63, rA = k >> 6, rB = 4 + (k >> 6);
    __syncthreads();

    const float* xgd = d_xg + (size_t)dir * Rc * Tc * G4c;
    for (int tau = 0; tau < Tc; ++tau){
        #pragma unroll
        for (int row = 0; row < 8; ++row){
            float acc = xgd[((r0+row)*Tc + tau)*G4c + k];
            #pragma unroll
            for (int hh = 0; hh < Hc; hh += 2){
                float2 hv = *(const float2*)&hsm[row][hh];
                acc += hv.x*w[hh] + hv.y*w[hh+1];
            }
            gsm[row][k] = acc;
        }
        __syncthreads();
        {
            float gi = gsm[rA][hid],      gf = gsm[rA][64+hid];
            float gg = gsm[rA][128+hid],  go = gsm[rA][192+hid];
            float cn = sigf(gf)*cc0 + sigf(gi)*tanhf(gg);
            float hn = sigf(go)*tanhf(cn);
            cc0 = cn; hsm[rA][hid] = hn;
            if (!L1) d_hs0[((dir*Rc + r0 + rA)*Tc + tau)*Hc + hid] = hn;
        }
        {
            float gi = gsm[rB][hid],      gf = gsm[rB][64+hid];
            float gg = gsm[rB][128+hid],  go = gsm[rB][192+hid];
            float cn = sigf(gf)*cc1 + sigf(gi)*tanhf(gg);
            float hn = sigf(go)*tanhf(cn);
            cc1 = cn; hsm[rB][hid] = hn;
            if (!L1) d_hs0[((dir*Rc + r0 + rB)*Tc + tau)*Hc + hid] = hn;
        }
        __syncthreads();
    }
    if (L1){
        d_hlast[(dir*Rc + r0 + rA)*Hc + hid] = hsm[rA][hid];
        d_hlast[(dir*Rc + r0 + rB)*Hc + hid] = hsm[rB][hid];
    }
}

// --------------------------- final FC ------------------------------------
__global__ void __launch_bounds__(128) k_fc(const float* __restrict__ fcW,
    const float* __restrict__ fcb, float* __restrict__ out)
{
    int r = blockIdx.x * blockDim.x + threadIdx.x;
    if (r >= Rc) return;
    float acc = fcb[0];
    #pragma unroll
    for (int hh = 0; hh < Hc; ++hh) acc += d_hlast[r*Hc + hh]       * fcW[hh];
    #pragma unroll
    for (int hh = 0; hh < Hc; ++hh) acc += d_hlast[(Rc + r)*Hc + hh] * fcW[64 + hh];
    out[r] = acc;
}

// --------------------------------------------------------------------------
extern "C" void kernel_launch(void* const* d_in, const int* in_sizes, int n_in,
                              void* d_out, int out_size)
{
    const float* x       = (const float*)d_in[0];
    const float* adj     = (const float*)d_in[1];
    const float* gat0_W  = (const float*)d_in[2];
    const float* gat0_a  = (const float*)d_in[3];
    const float* gat0_g  = (const float*)d_in[4];
    const float* gat0_b  = (const float*)d_in[5];
    const float* gat1_W  = (const float*)d_in[6];
    const float* gat1_a  = (const float*)d_in[7];
    const float* gat1_g  = (const float*)d_in[8];
    const float* gat1_b  = (const float*)d_in[9];
    const float* res_W   = (const float*)d_in[10];
    const float* res_b   = (const float*)d_in[11];
    const float* alpha   = (const float*)d_in[12];
    const float* l0_Wih  = (const float*)d_in[13];
    const float* l0_Whh  = (const float*)d_in[14];
    const float* l0_bih  = (const float*)d_in[15];
    const float* l0_bhh  = (const float*)d_in[16];
    const float* l1_Wih  = (const float*)d_in[17];
    const float* l1_Whh  = (const float*)d_in[18];
    const float* l1_bih  = (const float*)d_in[19];
    const float* l1_bhh  = (const float*)d_in[20];
    const float* fc_W    = (const float*)d_in[21];
    const float* fc_b    = (const float*)d_in[22];
    float* out = (float*)d_out;

    // GAT layer 0
    k_proj<Fc, false><<<Mc*Nc, 64>>>(x, gat0_W, gat0_a);
    k_attn<<<Mc*8, 256>>>(adj, gat0_g, gat0_b);
    // GAT layer 1
    k_proj<Hc, true><<<Mc*Nc, 64>>>(nullptr, gat1_W, gat1_a);
    k_attn<<<Mc*8, 256>>>(adj, gat1_g, gat1_b);
    // residual combine + transpose to sequences
    k_comb<<<Mc*Nc, 64>>>(x, res_W, res_b, alpha);
    // BiLSTM layer 0
    k_xg<Hc, false><<<dim3(Rc*16, 2), 256>>>(l0_Wih, l0_bih, l0_bhh);
    k_rec<false><<<dim3(Rc/8, 2), 256>>>(l0_Whh);
    // BiLSTM layer 1
    k_xg<2*Hc, true><<<dim3(Rc*16, 2), 256>>>(l1_Wih, l1_bih, l1_bhh);
    k_rec<true><<<dim3(Rc/8, 2), 256>>>(l1_Whh);
    // final FC
    k_fc<<<(Rc + 127)/128, 128>>>(fc_W, fc_b, out);
}

// round 3
// speedup vs baseline: 1.6255x; 1.6249x over previous
#include <cuda_runtime.h>
#include <math.h>

typedef unsigned long long ull;

// Problem constants
#define Bc 4
#define Sc 64
#define Nc 256
#define Fc 32
#define Hc 64
#define Mc (Bc*Sc)     // 256 graphs
#define Rc (Bc*Nc)     // 1024 sequences
#define Tc Sc          // 64 timesteps
#define G4c (4*Hc)     // 256 gate columns
#define NEGV (-9e15f)

// ---------------- device scratch ----------------
__device__ float d_h[Mc*Nc*Hc];
__device__ float d_g[Mc*Nc*Hc];
__device__ float d_si[Mc*Nc];
__device__ float d_sj[Mc*Nc];
__device__ float d_seq[Rc*Tc*Hc];
__device__ float d_xg[2*Rc*Tc*G4c];
__device__ float d_hs0[2*Rc*Tc*Hc];
__device__ float d_hlast[2*Rc*Hc];

__device__ __forceinline__ float warp_sum(float v){
    #pragma unroll
    for (int o=16;o;o>>=1) v += __shfl_xor_sync(0xffffffffu, v, o);
    return v;
}
__device__ __forceinline__ float warp_max(float v){
    #pragma unroll
    for (int o=16;o;o>>=1) v = fmaxf(v, __shfl_xor_sync(0xffffffffu, v, o));
    return v;
}
// packed f32x2 FMA (ptxas never auto-fuses this)
__device__ __forceinline__ void ffma2(ull& acc, ull a, ull b){
    asm("fma.rn.f32x2 %0, %1, %2, %0;" : "+l"(acc) : "l"(a), "l"(b));
}
__device__ __forceinline__ ull pack2(float x, float y){
    ull r; asm("mov.b64 %0, {%1, %2};" : "=l"(r) : "f"(x), "f"(y)); return r;
}
__device__ __forceinline__ float2 unpack2(ull v){
    float2 f; asm("mov.b64 {%0, %1}, %2;" : "=f"(f.x), "=f"(f.y) : "l"(v)); return f;
}
__device__ __forceinline__ float tanhfast(float x){
    float y; asm("tanh.approx.f32 %0, %1;" : "=f"(y) : "f"(x)); return y;
}
__device__ __forceinline__ float sigfast(float x){
    return fmaf(0.5f, tanhfast(0.5f*x), 0.5f);
}

// ---------------- GAT projection ----------------
template<int FIN_, bool FROM_G>
__global__ void __launch_bounds__(64) k_proj(const float* __restrict__ X,
    const float* __restrict__ W, const float* __restrict__ a)
{
    int row = blockIdx.x;
    int h = threadIdx.x;
    __shared__ float xr[FIN_];
    __shared__ float red[4];
    const float* src = FROM_G ? d_g : X;
    if (h < FIN_) xr[h] = src[row*FIN_ + h];
    __syncthreads();
    float acc = 0.f;
    #pragma unroll
    for (int f = 0; f < FIN_; ++f) acc += xr[f] * W[f*Hc + h];
    d_h[row*Hc + h] = acc;
    float v1 = warp_sum(acc * a[h]);
    float v2 = warp_sum(acc * a[Hc + h]);
    if ((h & 31) == 0){ red[h>>5] = v1; red[2 + (h>>5)] = v2; }
    __syncthreads();
    if (h == 0){ d_si[row] = red[0] + red[1]; d_sj[row] = red[2] + red[3]; }
}

// --------- GAT attention: one graph per block, warp-per-rows -------------
// dyn smem: h tile [256][64] (64KB) + p rows [8 warps][4 rows][256] (32KB) + sj (1KB)
#define ATTN_SMEM ((Nc*Hc + 8*4*Nc + Nc) * 4)
__global__ void __launch_bounds__(256) k_attn(const float* __restrict__ adj,
    const float* __restrict__ gamma, const float* __restrict__ beta)
{
    extern __shared__ float sm[];
    float* h_sm  = sm;                    // [256][64]
    float* p_sm  = sm + Nc*Hc;            // [8][4][256]
    float* sj_sm = p_sm + 8*4*Nc;         // [256]
    __shared__ float gb_sm[2*Hc];

    const int m = blockIdx.x;
    const int t = threadIdx.x, w = t>>5, lane = t&31;

    const float4* hg = (const float4*)(d_h + m*Nc*Hc);
    float4* h4 = (float4*)h_sm;
    #pragma unroll
    for (int i = 0; i < 16; ++i) h4[t + 256*i] = hg[t + 256*i];
    sj_sm[t] = d_sj[m*Nc + t];
    if (t < 64){ gb_sm[t] = gamma[t]; gb_sm[64+t] = beta[t]; }
    __syncthreads();

    float* pw = p_sm + w*(4*Nc);
    const float* hbase = h_sm + 2*lane;

    for (int g = 0; g < 8; ++g){
        // ---- softmax for 4 rows ----
        #pragma unroll
        for (int rr = 0; rr < 4; ++rr){
            int i = w*32 + g*4 + rr;
            float si = d_si[m*Nc + i];
            const float* arow = adj + ((size_t)m*Nc + i)*Nc;
            float ev[8]; float mx = -3.402823466e38f;
            #pragma unroll
            for (int q = 0; q < 8; ++q){
                int j = q*32 + lane;
                float e = si + sj_sm[j];
                e = e > 0.f ? e : 0.2f*e;
                if (arow[j] <= 0.f) e = NEGV;
                ev[q] = e; mx = fmaxf(mx, e);
            }
            mx = warp_max(mx);
            float s = 0.f;
            #pragma unroll
            for (int q = 0; q < 8; ++q){ ev[q] = __expf(ev[q]-mx); s += ev[q]; }
            s = warp_sum(s);
            float inv = 1.f / s;
            #pragma unroll
            for (int q = 0; q < 8; ++q) pw[rr*Nc + q*32 + lane] = ev[q]*inv;
        }
        __syncwarp();

        // ---- aggregate 4 rows x 64 cols; lane owns cols (2l, 2l+1) ----
        float acc[4][2];
        #pragma unroll
        for (int rr = 0; rr < 4; ++rr){ acc[rr][0] = 0.f; acc[rr][1] = 0.f; }
        #pragma unroll 2
        for (int j0 = 0; j0 < 256; j0 += 4){
            float4 p0 = *(const float4*)(pw + j0);
            float4 p1 = *(const float4*)(pw + Nc + j0);
            float4 p2 = *(const float4*)(pw + 2*Nc + j0);
            float4 p3 = *(const float4*)(pw + 3*Nc + j0);
            #pragma unroll
            for (int jj = 0; jj < 4; ++jj){
                float2 hv = *(const float2*)(hbase + (j0+jj)*Hc);
                float q0 = ((const float*)&p0)[jj];
                float q1 = ((const float*)&p1)[jj];
                float q2 = ((const float*)&p2)[jj];
                float q3 = ((const float*)&p3)[jj];
                acc[0][0] += q0*hv.x; acc[0][1] += q0*hv.y;
                acc[1][0] += q1*hv.x; acc[1][1] += q1*hv.y;
                acc[2][0] += q2*hv.x; acc[2][1] += q2*hv.y;
                acc[3][0] += q3*hv.x; acc[3][1] += q3*hv.y;
            }
        }
        __syncwarp();

        // ---- LayerNorm + ELU per row (all in-warp) ----
        float2 gmv = *(const float2*)(gb_sm + 2*lane);
        float2 btv = *(const float2*)(gb_sm + 64 + 2*lane);
        #pragma unroll
        for (int rr = 0; rr < 4; ++rr){
            float a0 = acc[rr][0], a1 = acc[rr][1];
            float s1 = warp_sum(a0 + a1);
            float s2 = warp_sum(a0*a0 + a1*a1);
            float mean = s1 * (1.f/64.f);
            float var  = s2 * (1.f/64.f) - mean*mean;
            float rstd = rsqrtf(var + 1e-5f);
            float h0 = (a0-mean)*rstd*gmv.x + btv.x;
            float h1 = (a1-mean)*rstd*gmv.y + btv.y;
            h0 = h0 > 0.f ? h0 : (__expf(h0) - 1.f);
            h1 = h1 > 0.f ? h1 : (__expf(h1) - 1.f);
            int i = w*32 + g*4 + rr;
            *(float2*)(d_g + (m*Nc + i)*Hc + 2*lane) = make_float2(h0, h1);
        }
    }
}

// ------- residual + gated combine + transpose -------
__global__ void __launch_bounds__(64) k_comb(const float* __restrict__ X,
    const float* __restrict__ Wr, const float* __restrict__ br,
    const float* __restrict__ alpha)
{
    int row = blockIdx.x;
    int m = row >> 8, n = row & 255;
    int b = m / Sc, s = m % Sc;
    int h = threadIdx.x;
    __shared__ float xr[Fc];
    if (h < Fc) xr[h] = X[row*Fc + h];
    __syncthreads();
    float acc = br[h];
    #pragma unroll
    for (int f = 0; f < Fc; ++f) acc += xr[f] * Wr[f*Hc + h];
    float gate = fminf(fmaxf(alpha[0], 0.f), 1.f);
    d_seq[((b*Nc + n)*Tc + s)*Hc + h] = acc + gate * d_g[row*Hc + h];
}

// ---------- LSTM input-gate precompute (f32x2, 16-tau blocking) ----------
// Block = (dir, seq r, tau-group of 16). Thread k owns one gate column.
#define TPAD 20
template<int IN_, bool L1>
__global__ void __launch_bounds__(256) k_xg(const float* __restrict__ Wih,
    const float* __restrict__ bih, const float* __restrict__ bhh)
{
    int dir = blockIdx.y;
    int r   = blockIdx.x >> 2;
    int tg  = blockIdx.x & 3;
    int k   = threadIdx.x;
    __shared__ float rowsT[IN_*TPAD];   // [hh][tau-in-group], padded stride

    for (int idx = k; idx < IN_*16; idx += 256){
        int hh = idx & (IN_-1);
        int q  = idx >> (IN_ == 64 ? 6 : 7);
        int tau = tg*16 + q;
        int tt = dir ? (Tc-1-tau) : tau;
        float v;
        if (!L1){
            v = d_seq[(r*Tc + tt)*Hc + hh];
        } else {
            if (hh < 64) v = d_hs0[(r*Tc + tt)*Hc + hh];
            else         v = d_hs0[((Rc + r)*Tc + (Tc-1-tt))*Hc + (hh-64)];
        }
        rowsT[hh*TPAD + q] = v;
    }
    __syncthreads();

    const float* Wd = Wih + dir*IN_*G4c;
    float bv = bih[dir*G4c + k] + bhh[dir*G4c + k];
    ull acc[8];
    #pragma unroll
    for (int i = 0; i < 8; ++i) acc[i] = pack2(bv, bv);

    #pragma unroll 4
    for (int hh = 0; hh < IN_; ++hh){
        float wv = Wd[hh*G4c + k];
        ull wd = pack2(wv, wv);
        const ulonglong2* rp = (const ulonglong2*)&rowsT[hh*TPAD];
        #pragma unroll
        for (int p = 0; p < 4; ++p){
            ulonglong2 rv = rp[p];
            ffma2(acc[2*p],   rv.x, wd);
            ffma2(acc[2*p+1], rv.y, wd);
        }
    }
    int base = ((dir*Rc + r)*Tc + tg*16)*G4c + k;
    #pragma unroll
    for (int p = 0; p < 8; ++p){
        float2 f = unpack2(acc[p]);
        d_xg[base + (2*p)*G4c]   = f.x;
        d_xg[base + (2*p+1)*G4c] = f.y;
    }
}

// ------------------------- LSTM recurrence (f32x2) -----------------------
// Block = (dir, 4 sequences). Thread k holds Whh column k as 32 f32x2 pairs.
template<bool L1>
__global__ void __launch_bounds__(256) k_rec(const float* __restrict__ Whh)
{
    int dir = blockIdx.y;
    int r0  = blockIdx.x * 4;
    int k   = threadIdx.x;
    __shared__ float hsm[4][Hc];
    __shared__ float gsm[4][G4c];

    ull w2[32];
    const float* Wd = Whh + dir*Hc*G4c;
    #pragma unroll
    for (int i = 0; i < 32; ++i)
        w2[i] = pack2(Wd[(2*i)*G4c + k], Wd[(2*i+1)*G4c + k]);

    hsm[k>>6][k&63] = 0.f;
    float cc = 0.f;
    const int hid = k & 63, row = k >> 6;
    __syncthreads();

    const float* xgd = d_xg + ((size_t)dir*Rc + r0)*Tc*G4c;
    for (int tau = 0; tau < Tc; ++tau){
        #pragma unroll
        for (int rr = 0; rr < 4; ++rr){
            ull a0 = pack2(xgd[(rr*Tc + tau)*G4c + k], 0.f);
            ull a1 = 0;  // {0,0}
            const ulonglong2* hp = (const ulonglong2*)hsm[rr];
            #pragma unroll
            for (int i = 0; i < 16; ++i){
                ulonglong2 hv = hp[i];
                ffma2(a0, hv.x, w2[2*i]);
                ffma2(a1, hv.y, w2[2*i+1]);
            }
            float2 f0 = unpack2(a0), f1 = unpack2(a1);
            gsm[rr][k] = (f0.x + f1.x) + (f0.y + f1.y);
        }
        __syncthreads();
        float gi = gsm[row][hid],     gf = gsm[row][64+hid];
        float gg = gsm[row][128+hid], go = gsm[row][192+hid];
        float cn = sigfast(gf)*cc + sigfast(gi)*tanhfast(gg);
        float hn = sigfast(go)*tanhfast(cn);
        cc = cn;
        hsm[row][hid] = hn;
        if (!L1) d_hs0[((dir*Rc + r0 + row)*Tc + tau)*Hc + hid] = hn;
        __syncthreads();
    }
    if (L1) d_hlast[(dir*Rc + r0 + row)*Hc + hid] = hsm[row][hid];
}

// --------------------------- final FC ------------------------------------
__global__ void __launch_bounds__(128) k_fc(const float* __restrict__ fcW,
    const float* __restrict__ fcb, float* __restrict__ out)
{
    int r = blockIdx.x * blockDim.x + threadIdx.x;
    if (r >= Rc) return;
    float acc = fcb[0];
    #pragma unroll
    for (int hh = 0; hh < Hc; ++hh) acc += d_hlast[r*Hc + hh]        * fcW[hh];
    #pragma unroll
    for (int hh = 0; hh < Hc; ++hh) acc += d_hlast[(Rc + r)*Hc + hh] * fcW[64 + hh];
    out[r] = acc;
}

// --------------------------------------------------------------------------
extern "C" void kernel_launch(void* const* d_in, const int* in_sizes, int n_in,
                              void* d_out, int out_size)
{
    const float* x       = (const float*)d_in[0];
    const float* adj     = (const float*)d_in[1];
    const float* gat0_W  = (const float*)d_in[2];
    const float* gat0_a  = (const float*)d_in[3];
    const float* gat0_g  = (const float*)d_in[4];
    const float* gat0_b  = (const float*)d_in[5];
    const float* gat1_W  = (const float*)d_in[6];
    const float* gat1_a  = (const float*)d_in[7];
    const float* gat1_g  = (const float*)d_in[8];
    const float* gat1_b  = (const float*)d_in[9];
    const float* res_W   = (const float*)d_in[10];
    const float* res_b   = (const float*)d_in[11];
    const float* alpha   = (const float*)d_in[12];
    const float* l0_Wih  = (const float*)d_in[13];
    const float* l0_Whh  = (const float*)d_in[14];
    const float* l0_bih  = (const float*)d_in[15];
    const float* l0_bhh  = (const float*)d_in[16];
    const float* l1_Wih  = (const float*)d_in[17];
    const float* l1_Whh  = (const float*)d_in[18];
    const float* l1_bih  = (const float*)d_in[19];
    const float* l1_bhh  = (const float*)d_in[20];
    const float* fc_W    = (const float*)d_in[21];
    const float* fc_b    = (const float*)d_in[22];
    float* out = (float*)d_out;

    cudaFuncSetAttribute(k_attn, cudaFuncAttributeMaxDynamicSharedMemorySize, ATTN_SMEM);

    // GAT layer 0
    k_proj<Fc, false><<<Mc*Nc, 64>>>(x, gat0_W, gat0_a);
    k_attn<<<Mc, 256, ATTN_SMEM>>>(adj, gat0_g, gat0_b);
    // GAT layer 1
    k_proj<Hc, true><<<Mc*Nc, 64>>>(nullptr, gat1_W, gat1_a);
    k_attn<<<Mc, 256, ATTN_SMEM>>>(adj, gat1_g, gat1_b);
    // residual combine + transpose to sequences
    k_comb<<<Mc*Nc, 64>>>(x, res_W, res_b, alpha);
    // BiLSTM layer 0
    k_xg<Hc, false><<<dim3(Rc*4, 2), 256>>>(l0_Wih, l0_bih, l0_bhh);
    k_rec<false><<<dim3(Rc/4, 2), 256>>>(l0_Whh);
    // BiLSTM layer 1
    k_xg<2*Hc, true><<<dim3(Rc*4, 2), 256>>>(l1_Wih, l1_bih, l1_bhh);
    k_rec<true><<<dim3(Rc/4, 2), 256>>>(l1_Whh);
    // final FC
    k_fc<<<(Rc + 127)/128, 128>>>(fc_W, fc_b, out);
}

// round 6
// speedup vs baseline: 1.6815x; 1.0345x over previous
#include <cuda_runtime.h>
#include <math.h>

typedef unsigned long long ull;

#define Bc 4
#define Sc 64
#define Nc 256
#define Fc 32
#define Hc 64
#define Mc (Bc*Sc)     // 256 graphs
#define Rc (Bc*Nc)     // 1024 sequences
#define Tc Sc          // 64 timesteps
#define G4c (4*Hc)     // 256 gate columns
#define NEGV (-9e15f)

// ---------------- device scratch ----------------
__device__ float d_h[Mc*Nc*Hc];          // row-major [m][n][h]
__device__ float d_g[Mc*Nc*Hc];          // row-major [m][n][h]
__device__ float d_si[Mc*Nc];
__device__ float d_sj[Mc*Nc];
__device__ float d_seq[Rc*Tc*Hc];
__device__ float d_xg[2*Rc*Tc*G4c];
__device__ float d_hs0[2*Rc*Tc*Hc];
__device__ float d_hlast[2*Rc*Hc];

__device__ __forceinline__ float warp_sum(float v){
    #pragma unroll
    for (int o=16;o;o>>=1) v += __shfl_xor_sync(0xffffffffu, v, o);
    return v;
}
__device__ __forceinline__ float warp_max(float v){
    #pragma unroll
    for (int o=16;o;o>>=1) v = fmaxf(v, __shfl_xor_sync(0xffffffffu, v, o));
    return v;
}
__device__ __forceinline__ void ffma2(ull& acc, ull a, ull b){
    asm("fma.rn.f32x2 %0, %1, %2, %0;" : "+l"(acc) : "l"(a), "l"(b));
}
__device__ __forceinline__ ull pack2(float x, float y){
    ull r; asm("mov.b64 %0, {%1, %2};" : "=l"(r) : "f"(x), "f"(y)); return r;
}
__device__ __forceinline__ float2 unpack2(ull v){
    float2 f; asm("mov.b64 {%0, %1}, %2;" : "=f"(f.x), "=f"(f.y) : "l"(v)); return f;
}
__device__ __forceinline__ float tanhfast(float x){
    float y; asm("tanh.approx.f32 %0, %1;" : "=f"(y) : "f"(x)); return y;
}
__device__ __forceinline__ float sigfast(float x){
    return fmaf(0.5f, tanhfast(0.5f*x), 0.5f);
}

// ---------------- GAT projection (R2-proven) ----------------
template<int FIN_, bool FROM_G>
__global__ void __launch_bounds__(64) k_proj(const float* __restrict__ X,
    const float* __restrict__ W, const float* __restrict__ a)
{
    int row = blockIdx.x;
    int h = threadIdx.x;
    __shared__ float xr[FIN_];
    __shared__ float red[4];
    const float* src = FROM_G ? d_g : X;
    if (h < FIN_) xr[h] = src[(size_t)row*FIN_ + h];
    __syncthreads();
    float acc = 0.f;
    #pragma unroll
    for (int f = 0; f < FIN_; ++f) acc += xr[f] * W[f*Hc + h];
    d_h[(size_t)row*Hc + h] = acc;
    float v1 = warp_sum(acc * a[h]);
    float v2 = warp_sum(acc * a[Hc + h]);
    if ((h & 31) == 0){ red[h>>5] = v1; red[2 + (h>>5)] = v2; }
    __syncthreads();
    if (h == 0){ d_si[row] = red[0] + red[1]; d_sj[row] = red[2] + red[3]; }
}

// --------- GAT attention: transpose-on-load, j-packed f32x2 --------------
#define HST 264                                     // padded j-stride (floats)
#define ATTN_SMEM ((Hc*HST + 8*4*Nc + 2*Nc) * 4)    // ~100 KB
__global__ void __launch_bounds__(256) k_attn(const float* __restrict__ adj,
    const float* __restrict__ gamma, const float* __restrict__ beta)
{
    extern __shared__ float sm[];
    float* h_smT = sm;                    // [h=64][j], stride HST
    float* p_sm  = sm + Hc*HST;           // [8 warps][4 rows][256]
    float* si_sm = p_sm + 8*4*Nc;         // [256]
    float* sj_sm = si_sm + Nc;            // [256]

    const int m = blockIdx.x;
    const int t = threadIdx.x, w = t>>5, lane = t&31;

    // transpose d_h [n][h] -> h_smT[h][n]; component rotation -> 4-way conflicts
    const float4* hg4 = (const float4*)(d_h + (size_t)m*Nc*Hc);
    #pragma unroll
    for (int i = 0; i < 16; ++i){
        int f4 = t + 256*i;
        int n  = f4 >> 4;             // node index
        int hq = f4 & 15;             // h-quad, h0 = 4*hq
        float4 v = hg4[f4];
        #pragma unroll
        for (int u = 0; u < 4; ++u){
            int c = (u + hq) & 3;     // component & h-offset for this slot
            float a0 = (c & 1) ? v.y : v.x;
            float a1 = (c & 1) ? v.w : v.z;
            float val = (c & 2) ? a1 : a0;
            h_smT[(4*hq + c)*HST + n] = val;
        }
    }
    si_sm[t] = d_si[m*Nc + t];
    sj_sm[t] = d_sj[m*Nc + t];
    __syncthreads();

    const float gm0 = gamma[lane], gm1 = gamma[lane+32];
    const float bt0 = beta[lane],  bt1 = beta[lane+32];
    float* pw = p_sm + w*(4*Nc);
    const float* hA_base = h_smT + lane*HST;
    const float* hB_base = h_smT + (lane+32)*HST;

    for (int g = 0; g < 8; ++g){
        // ---- softmax for this warp's 4 rows ----
        #pragma unroll
        for (int rr = 0; rr < 4; ++rr){
            int i = w*32 + g*4 + rr;
            float si = si_sm[i];
            const float* arow = adj + ((size_t)m*Nc + i)*Nc;
            float ev[8]; float mx = -3.402823466e38f;
            #pragma unroll
            for (int q = 0; q < 8; ++q){
                int j = q*32 + lane;
                float e = si + sj_sm[j];
                e = e > 0.f ? e : 0.2f*e;
                if (arow[j] <= 0.f) e = NEGV;
                ev[q] = e; mx = fmaxf(mx, e);
            }
            mx = warp_max(mx);
            float s = 0.f;
            #pragma unroll
            for (int q = 0; q < 8; ++q){ ev[q] = __expf(ev[q]-mx); s += ev[q]; }
            s = warp_sum(s);
            float inv = 1.f / s;
            #pragma unroll
            for (int q = 0; q < 8; ++q) pw[rr*Nc + q*32 + lane] = ev[q]*inv;
        }
        __syncwarp();

        // ---- aggregation: packed over j pairs; lane owns cols (l, l+32) ----
        ull acc[4][2];
        #pragma unroll
        for (int rr = 0; rr < 4; ++rr){ acc[rr][0] = 0; acc[rr][1] = 0; }
        #pragma unroll 2
        for (int j0 = 0; j0 < 256; j0 += 4){
            ulonglong2 hA = *(const ulonglong2*)(hA_base + j0);
            ulonglong2 hB = *(const ulonglong2*)(hB_base + j0);
            #pragma unroll
            for (int rr = 0; rr < 4; ++rr){
                ulonglong2 pp = *(const ulonglong2*)(pw + rr*Nc + j0);
                ffma2(acc[rr][0], pp.x, hA.x);
                ffma2(acc[rr][0], pp.y, hA.y);
                ffma2(acc[rr][1], pp.x, hB.x);
                ffma2(acc[rr][1], pp.y, hB.y);
            }
        }
        __syncwarp();

        // ---- LayerNorm + ELU ----
        #pragma unroll
        for (int rr = 0; rr < 4; ++rr){
            float2 u0 = unpack2(acc[rr][0]);
            float2 u1 = unpack2(acc[rr][1]);
            float a0 = u0.x + u0.y, a1 = u1.x + u1.y;
            float s1 = warp_sum(a0 + a1);
            float s2 = warp_sum(a0*a0 + a1*a1);
            float mean = s1 * (1.f/64.f);
            float var  = s2 * (1.f/64.f) - mean*mean;
            float rstd = rsqrtf(var + 1e-5f);
            float e0 = (a0-mean)*rstd*gm0 + bt0;
            float e1 = (a1-mean)*rstd*gm1 + bt1;
            e0 = e0 > 0.f ? e0 : (__expf(e0) - 1.f);
            e1 = e1 > 0.f ? e1 : (__expf(e1) - 1.f);
            int i = w*32 + g*4 + rr;
            d_g[((size_t)m*Nc + i)*Hc + lane]      = e0;
            d_g[((size_t)m*Nc + i)*Hc + lane + 32] = e1;
        }
    }
}

// ------- residual + gated combine + transpose (4 rows / block) -----------
__global__ void __launch_bounds__(256) k_comb(const float* __restrict__ X,
    const float* __restrict__ Wr, const float* __restrict__ br,
    const float* __restrict__ alpha)
{
    const int t = threadIdx.x;
    const int row = blockIdx.x*4 + (t>>6);
    const int h = t & 63;
    __shared__ float xr[4][Fc+1];
    if (t < 128){
        int rr = t>>5, f = t&31;
        xr[rr][f] = X[(size_t)(blockIdx.x*4 + rr)*Fc + f];
    }
    __syncthreads();
    const int rr = t>>6;
    float acc = br[h];
    #pragma unroll
    for (int f = 0; f < Fc; ++f) acc += xr[rr][f] * Wr[f*Hc + h];
    float gate = fminf(fmaxf(alpha[0], 0.f), 1.f);
    int m = row >> 8, n = row & 255;
    int b = m >> 6, s = m & 63;
    d_seq[(((size_t)b*Nc + n)*Tc + s)*Hc + h] = acc + gate * d_g[(size_t)row*Hc + h];
}

// ---------- LSTM input gates: both directions share the row tile ----------
// Block = (seq r, input-time half). Covers input times it = half*32 + q.
// dir0 scan tau = it; dir1 scan tau = 63 - it.
#define XPAD 36
template<int IN_, bool L1>
__global__ void __launch_bounds__(256) k_xg(const float* __restrict__ Wih,
    const float* __restrict__ bih, const float* __restrict__ bhh)
{
    const int r    = blockIdx.x >> 1;
    const int half = blockIdx.x & 1;
    const int k    = threadIdx.x;
    __shared__ __align__(16) float rowsT[IN_*XPAD];   // [hh][q]

    #pragma unroll
    for (int i = 0; i < IN_/8; ++i){
        int idx = k + 256*i;
        int hh = idx & (IN_-1);
        int q  = idx >> (IN_==64?6:7);
        int it = half*32 + q;
        float v;
        if (!L1){
            v = d_seq[((size_t)r*Tc + it)*Hc + hh];
        } else {
            if (hh < 64) v = d_hs0[((size_t)r*Tc + it)*Hc + hh];
            else         v = d_hs0[(((size_t)Rc + r)*Tc + (Tc-1-it))*Hc + (hh-64)];
        }
        rowsT[hh*XPAD + q] = v;
    }
    __syncthreads();

    const float* WA = Wih;
    const float* WB = Wih + IN_*G4c;
    float bvA = bih[k] + bhh[k];
    float bvB = bih[G4c + k] + bhh[G4c + k];
    ull accA[16], accB[16];
    #pragma unroll
    for (int i = 0; i < 16; ++i){ accA[i] = pack2(bvA,bvA); accB[i] = pack2(bvB,bvB); }

    #pragma unroll 2
    for (int hh = 0; hh < IN_; ++hh){
        float wa = WA[hh*G4c + k];
        float wb = WB[hh*G4c + k];
        ull wda = pack2(wa,wa), wdb = pack2(wb,wb);
        const ulonglong2* rp = (const ulonglong2*)&rowsT[hh*XPAD];
        #pragma unroll
        for (int p = 0; p < 4; ++p){
            ulonglong2 rv = rp[p];
            ffma2(accA[4*p],   rv.x, wda);
            ffma2(accA[4*p+1], rv.y, wda);
            ffma2(accB[4*p],   rv.x, wdb);
            ffma2(accB[4*p+1], rv.y, wdb);
        }
        const ulonglong2* rp2 = rp + 4;
        #pragma unroll
        for (int p = 0; p < 4; ++p){
            ulonglong2 rv = rp2[p];
            ffma2(accA[4*p+2], rv.x, wda);
            ffma2(accA[4*p+3], rv.y, wda);
            ffma2(accB[4*p+2], rv.x, wdb);
            ffma2(accB[4*p+3], rv.y, wdb);
        }
    }

    // accA[4p]:q(4p,4p+1)  accA[4p+1]:q(4p+2,4p+3)
    // accA[4p+2]:q(16+4p,+1)  accA[4p+3]:q(16+4p+2,+3)
    #pragma unroll
    for (int p = 0; p < 4; ++p){
        #pragma unroll
        for (int u = 0; u < 4; ++u){
            int q = (u < 2) ? (4*p + 2*u) : (16 + 4*p + 2*(u-2));
            float2 fa = unpack2(accA[4*p+u]);
            float2 fb = unpack2(accB[4*p+u]);
            int it0 = half*32 + q;
            size_t b0 = ((size_t)r*Tc + it0)*G4c + k;
            d_xg[b0]       = fa.x;
            d_xg[b0 + G4c] = fa.y;
            size_t b1 = (((size_t)Rc + r)*Tc + (Tc-1-it0))*G4c + k;
            d_xg[b1]       = fb.x;
            d_xg[b1 - G4c] = fb.y;
        }
    }
}

// ------------------------- LSTM recurrence (f32x2, R2-proven) ------------
template<bool L1>
__global__ void __launch_bounds__(256) k_rec(const float* __restrict__ Whh)
{
    int dir = blockIdx.y;
    int r0  = blockIdx.x * 4;
    int k   = threadIdx.x;
    __shared__ __align__(16) float hsm[4][Hc];
    __shared__ float gsm[4][G4c];

    ull w2[32];
    const float* Wd = Whh + dir*Hc*G4c;
    #pragma unroll
    for (int i = 0; i < 32; ++i)
        w2[i] = pack2(Wd[(2*i)*G4c + k], Wd[(2*i+1)*G4c + k]);

    hsm[k>>6][k&63] = 0.f;
    float cc = 0.f;
    const int hid = k & 63, row = k >> 6;
    __syncthreads();

    const float* xgd = d_xg + ((size_t)dir*Rc + r0)*Tc*G4c;
    for (int tau = 0; tau < Tc; ++tau){
        #pragma unroll
        for (int rr = 0; rr < 4; ++rr){
            ull a0 = pack2(xgd[((size_t)rr*Tc + tau)*G4c + k], 0.f);
            ull a1 = 0;
            const ulonglong2* hp = (const ulonglong2*)hsm[rr];
            #pragma unroll
            for (int i = 0; i < 16; ++i){
                ulonglong2 hv = hp[i];
                ffma2(a0, hv.x, w2[2*i]);
                ffma2(a1, hv.y, w2[2*i+1]);
            }
            float2 f0 = unpack2(a0), f1 = unpack2(a1);
            gsm[rr][k] = (f0.x + f1.x) + (f0.y + f1.y);
        }
        __syncthreads();
        float gi = gsm[row][hid],     gf = gsm[row][64+hid];
        float gg = gsm[row][128+hid], go = gsm[row][192+hid];
        float cn = sigfast(gf)*cc + sigfast(gi)*tanhfast(gg);
        float hn = sigfast(go)*tanhfast(cn);
        cc = cn;
        hsm[row][hid] = hn;
        if (!L1) d_hs0[((size_t)(dir*Rc + r0 + row)*Tc + tau)*Hc + hid] = hn;
        __syncthreads();
    }
    if (L1) d_hlast[(size_t)(dir*Rc + r0 + row)*Hc + hid] = hsm[row][hid];
}

// --------------------------- final FC ------------------------------------
__global__ void __launch_bounds__(128) k_fc(const float* __restrict__ fcW,
    const float* __restrict__ fcb, float* __restrict__ out)
{
    int r = blockIdx.x * blockDim.x + threadIdx.x;
    if (r >= Rc) return;
    float acc = fcb[0];
    #pragma unroll
    for (int hh = 0; hh < Hc; ++hh) acc += d_hlast[(size_t)r*Hc + hh]        * fcW[hh];
    #pragma unroll
    for (int hh = 0; hh < Hc; ++hh) acc += d_hlast[((size_t)Rc + r)*Hc + hh] * fcW[64 + hh];
    out[r] = acc;
}

// --------------------------------------------------------------------------
extern "C" void kernel_launch(void* const* d_in, const int* in_sizes, int n_in,
                              void* d_out, int out_size)
{
    const float* x       = (const float*)d_in[0];
    const float* adj     = (const float*)d_in[1];
    const float* gat0_W  = (const float*)d_in[2];
    const float* gat0_a  = (const float*)d_in[3];
    const float* gat0_g  = (const float*)d_in[4];
    const float* gat0_b  = (const float*)d_in[5];
    const float* gat1_W  = (const float*)d_in[6];
    const float* gat1_a  = (const float*)d_in[7];
    const float* gat1_g  = (const float*)d_in[8];
    const float* gat1_b  = (const float*)d_in[9];
    const float* res_W   = (const float*)d_in[10];
    const float* res_b   = (const float*)d_in[11];
    const float* alpha   = (const float*)d_in[12];
    const float* l0_Wih  = (const float*)d_in[13];
    const float* l0_Whh  = (const float*)d_in[14];
    const float* l0_bih  = (const float*)d_in[15];
    const float* l0_bhh  = (const float*)d_in[16];
    const float* l1_Wih  = (const float*)d_in[17];
    const float* l1_Whh  = (const float*)d_in[18];
    const float* l1_bih  = (const float*)d_in[19];
    const float* l1_bhh  = (const float*)d_in[20];
    const float* fc_W    = (const float*)d_in[21];
    const float* fc_b    = (const float*)d_in[22];
    float* out = (float*)d_out;

    cudaFuncSetAttribute(k_attn, cudaFuncAttributeMaxDynamicSharedMemorySize, ATTN_SMEM);

    // GAT layer 0
    k_proj<Fc, false><<<Mc*Nc, 64>>>(x, gat0_W, gat0_a);
    k_attn<<<Mc, 256, ATTN_SMEM>>>(adj, gat0_g, gat0_b);
    // GAT layer 1
    k_proj<Hc, true><<<Mc*Nc, 64>>>(nullptr, gat1_W, gat1_a);
    k_attn<<<Mc, 256, ATTN_SMEM>>>(adj, gat1_g, gat1_b);
    // residual combine + transpose to sequences
    k_comb<<<Mc*Nc/4, 256>>>(x, res_W, res_b, alpha);
    // BiLSTM layer 0
    k_xg<Hc,   false><<<Rc*2, 256>>>(l0_Wih, l0_bih, l0_bhh);
    k_rec<false><<<dim3(Rc/4, 2), 256>>>(l0_Whh);
    // BiLSTM layer 1
    k_xg<2*Hc, true><<<Rc*2, 256>>>(l1_Wih, l1_bih, l1_bhh);
    k_rec<true><<<dim3(Rc/4, 2), 256>>>(l1_Whh);
    // final FC
    k_fc<<<(Rc + 127)/128, 128>>>(fc_W, fc_b, out);
}

// round 9
// speedup vs baseline: 1.7816x; 1.0595x over previous
#include <cuda_runtime.h>
#include <math.h>

typedef unsigned long long ull;

#define Bc 4
#define Sc 64
#define Nc 256
#define Fc 32
#define Hc 64
#define Mc (Bc*Sc)     // 256 graphs
#define Rc (Bc*Nc)     // 1024 sequences
#define Tc Sc          // 64 timesteps
#define G4c (4*Hc)     // 256 gate columns
#define NEGV (-9e15f)

// ---------------- device scratch ----------------
__device__ float d_h[Mc*Nc*Hc];          // row-major [m][n][h]
__device__ float d_g[Mc*Nc*Hc];          // row-major [m][n][h]
__device__ float d_si[Mc*Nc];
__device__ float d_sj[Mc*Nc];
__device__ float d_seq[Rc*Tc*Hc];
__device__ float d_xg[2*Rc*Tc*G4c];
__device__ float d_hs0[2*Rc*Tc*Hc];
__device__ float d_hlast[2*Rc*Hc];

__device__ __forceinline__ float warp_sum(float v){
    #pragma unroll
    for (int o=16;o;o>>=1) v += __shfl_xor_sync(0xffffffffu, v, o);
    return v;
}
__device__ __forceinline__ float warp_max(float v){
    #pragma unroll
    for (int o=16;o;o>>=1) v = fmaxf(v, __shfl_xor_sync(0xffffffffu, v, o));
    return v;
}
__device__ __forceinline__ void ffma2(ull& acc, ull a, ull b){
    asm("fma.rn.f32x2 %0, %1, %2, %0;" : "+l"(acc) : "l"(a), "l"(b));
}
__device__ __forceinline__ ull pack2(float x, float y){
    ull r; asm("mov.b64 %0, {%1, %2};" : "=l"(r) : "f"(x), "f"(y)); return r;
}
__device__ __forceinline__ float2 unpack2(ull v){
    float2 f; asm("mov.b64 {%0, %1}, %2;" : "=f"(f.x), "=f"(f.y) : "l"(v)); return f;
}
__device__ __forceinline__ float tanhfast(float x){
    float y; asm("tanh.approx.f32 %0, %1;" : "=f"(y) : "f"(x)); return y;
}
__device__ __forceinline__ float sigfast(float x){
    return fmaf(0.5f, tanhfast(0.5f*x), 0.5f);
}

// ---------------- GAT projection: 4 rows per block ----------------
template<int FIN_, bool FROM_G>
__global__ void __launch_bounds__(256) k_proj(const float* __restrict__ X,
    const float* __restrict__ W, const float* __restrict__ a)
{
    const int t = threadIdx.x;
    const int grp = t >> 6, h = t & 63;
    const int row0 = blockIdx.x * 4;
    __shared__ float xr[4][FIN_];
    __shared__ float red2[2][4][2];      // [si|sj][grp][warp-in-grp]
    const float* src = FROM_G ? d_g : X;
    #pragma unroll
    for (int i = 0; i < (4*FIN_+255)/256; ++i){
        int idx = t + 256*i;
        if (idx < 4*FIN_){
            int rr = idx / FIN_, f = idx % FIN_;
            xr[rr][f] = src[(size_t)(row0+rr)*FIN_ + f];
        }
    }
    __syncthreads();
    float acc = 0.f;
    #pragma unroll
    for (int f = 0; f < FIN_; ++f) acc += xr[grp][f] * W[f*Hc + h];
    d_h[(size_t)(row0+grp)*Hc + h] = acc;
    float v1 = warp_sum(acc * a[h]);
    float v2 = warp_sum(acc * a[Hc + h]);
    const int wig = (t >> 5) & 1;
    if ((t & 31) == 0){ red2[0][grp][wig] = v1; red2[1][grp][wig] = v2; }
    __syncthreads();
    if (h == 0){
        d_si[row0+grp] = red2[0][grp][0] + red2[0][grp][1];
        d_sj[row0+grp] = red2[1][grp][0] + red2[1][grp][1];
    }
}

// --------- GAT attention: transpose-on-load, conflict-free f32x2 ---------
#define HST 268                                     // 67 (16B units) ≡ 3 mod 8 → conflict-free
#define ATTN_SMEM ((Hc*HST + 8*4*Nc + 2*Nc) * 4)
__global__ void __launch_bounds__(256) k_attn(const float* __restrict__ adj,
    const float* __restrict__ gamma, const float* __restrict__ beta)
{
    extern __shared__ float sm[];
    float* h_smT = sm;                    // [h=64][j], stride HST
    float* p_sm  = sm + Hc*HST;           // [8 warps][4 rows][256]
    float* si_sm = p_sm + 8*4*Nc;         // [256]
    float* sj_sm = si_sm + Nc;            // [256]

    const int m = blockIdx.x;
    const int half = blockIdx.y;          // 0: rows 0..127, 1: rows 128..255
    const int t = threadIdx.x, w = t>>5, lane = t&31;

    // transpose d_h [n][h] -> h_smT[h][n]; component rotation limits conflicts
    const float4* hg4 = (const float4*)(d_h + (size_t)m*Nc*Hc);
    #pragma unroll
    for (int i = 0; i < 16; ++i){
        int f4 = t + 256*i;
        int n  = f4 >> 4;
        int hq = f4 & 15;
        float4 v = hg4[f4];
        #pragma unroll
        for (int u = 0; u < 4; ++u){
            int c = (u + hq) & 3;
            float a0 = (c & 1) ? v.y : v.x;
            float a1 = (c & 1) ? v.w : v.z;
            float val = (c & 2) ? a1 : a0;
            h_smT[(4*hq + c)*HST + n] = val;
        }
    }
    si_sm[t] = d_si[m*Nc + t];
    sj_sm[t] = d_sj[m*Nc + t];
    __syncthreads();

    const float gm0 = gamma[lane], gm1 = gamma[lane+32];
    const float bt0 = beta[lane],  bt1 = beta[lane+32];
    float* pw = p_sm + w*(4*Nc);
    const float* hA_base = h_smT + lane*HST;
    const float* hB_base = h_smT + (lane+32)*HST;

    for (int g = 0; g < 4; ++g){
        // ---- softmax for this warp's 4 rows ----
        #pragma unroll
        for (int rr = 0; rr < 4; ++rr){
            int i = half*128 + w*16 + g*4 + rr;
            float si = si_sm[i];
            const float* arow = adj + ((size_t)m*Nc + i)*Nc;
            float ev[8]; float mx = -3.402823466e38f;
            #pragma unroll
            for (int q = 0; q < 8; ++q){
                int j = q*32 + lane;
                float e = si + sj_sm[j];
                e = e > 0.f ? e : 0.2f*e;
                if (arow[j] <= 0.f) e = NEGV;
                ev[q] = e; mx = fmaxf(mx, e);
            }
            mx = warp_max(mx);
            float s = 0.f;
            #pragma unroll
            for (int q = 0; q < 8; ++q){ ev[q] = __expf(ev[q]-mx); s += ev[q]; }
            s = warp_sum(s);
            float inv = 1.f / s;
            #pragma unroll
            for (int q = 0; q < 8; ++q) pw[rr*Nc + q*32 + lane] = ev[q]*inv;
        }
        __syncwarp();

        // ---- aggregation: packed over j pairs; lane owns cols (l, l+32) ----
        ull acc[4][2];
        #pragma unroll
        for (int rr = 0; rr < 4; ++rr){ acc[rr][0] = 0; acc[rr][1] = 0; }
        #pragma unroll 4
        for (int j0 = 0; j0 < 256; j0 += 4){
            ulonglong2 hA = *(const ulonglong2*)(hA_base + j0);
            ulonglong2 hB = *(const ulonglong2*)(hB_base + j0);
            #pragma unroll
            for (int rr = 0; rr < 4; ++rr){
                ulonglong2 pp = *(const ulonglong2*)(pw + rr*Nc + j0);
                ffma2(acc[rr][0], pp.x, hA.x);
                ffma2(acc[rr][0], pp.y, hA.y);
                ffma2(acc[rr][1], pp.x, hB.x);
                ffma2(acc[rr][1], pp.y, hB.y);
            }
        }
        __syncwarp();

        // ---- LayerNorm + ELU ----
        #pragma unroll
        for (int rr = 0; rr < 4; ++rr){
            float2 u0 = unpack2(acc[rr][0]);
            float2 u1 = unpack2(acc[rr][1]);
            float a0 = u0.x + u0.y, a1 = u1.x + u1.y;
            float s1 = warp_sum(a0 + a1);
            float s2 = warp_sum(a0*a0 + a1*a1);
            float mean = s1 * (1.f/64.f);
            float var  = s2 * (1.f/64.f) - mean*mean;
            float rstd = rsqrtf(var + 1e-5f);
            float e0 = (a0-mean)*rstd*gm0 + bt0;
            float e1 = (a1-mean)*rstd*gm1 + bt1;
            e0 = e0 > 0.f ? e0 : (__expf(e0) - 1.f);
            e1 = e1 > 0.f ? e1 : (__expf(e1) - 1.f);
            int i = half*128 + w*16 + g*4 + rr;
            d_g[((size_t)m*Nc + i)*Hc + lane]      = e0;
            d_g[((size_t)m*Nc + i)*Hc + lane + 32] = e1;
        }
    }
}

// ------- residual + gated combine + transpose (4 rows / block) -----------
__global__ void __launch_bounds__(256) k_comb(const float* __restrict__ X,
    const float* __restrict__ Wr, const float* __restrict__ br,
    const float* __restrict__ alpha)
{
    const int t = threadIdx.x;
    const int row = blockIdx.x*4 + (t>>6);
    const int h = t & 63;
    __shared__ float xr[4][Fc+1];
    if (t < 128){
        int rr = t>>5, f = t&31;
        xr[rr][f] = X[(size_t)(blockIdx.x*4 + rr)*Fc + f];
    }
    __syncthreads();
    const int rr = t>>6;
    float acc = br[h];
    #pragma unroll
    for (int f = 0; f < Fc; ++f) acc += xr[rr][f] * Wr[f*Hc + h];
    float gate = fminf(fmaxf(alpha[0], 0.f), 1.f);
    int m = row >> 8, n = row & 255;
    int b = m >> 6, s = m & 63;
    d_seq[(((size_t)b*Nc + n)*Tc + s)*Hc + h] = acc + gate * d_g[(size_t)row*Hc + h];
}

// ---------- LSTM input gates: both directions share the row tile ----------
#define XPAD 36
template<int IN_, bool L1>
__global__ void __launch_bounds__(256) k_xg(const float* __restrict__ Wih,
    const float* __restrict__ bih, const float* __restrict__ bhh)
{
    const int r    = blockIdx.x >> 1;
    const int half = blockIdx.x & 1;
    const int k    = threadIdx.x;
    __shared__ __align__(16) float rowsT[IN_*XPAD];   // [hh][q]

    #pragma unroll
    for (int i = 0; i < IN_/8; ++i){
        int idx = k + 256*i;
        int hh = idx & (IN_-1);
        int q  = idx >> (IN_==64?6:7);
        int it = half*32 + q;
        float v;
        if (!L1){
            v = d_seq[((size_t)r*Tc + it)*Hc + hh];
        } else {
            if (hh < 64) v = d_hs0[((size_t)r*Tc + it)*Hc + hh];
            else         v = d_hs0[(((size_t)Rc + r)*Tc + (Tc-1-it))*Hc + (hh-64)];
        }
        rowsT[hh*XPAD + q] = v;
    }
    __syncthreads();

    const float* WA = Wih;
    const float* WB = Wih + IN_*G4c;
    float bvA = bih[k] + bhh[k];
    float bvB = bih[G4c + k] + bhh[G4c + k];
    ull accA[16], accB[16];
    #pragma unroll
    for (int i = 0; i < 16; ++i){ accA[i] = pack2(bvA,bvA); accB[i] = pack2(bvB,bvB); }

    #pragma unroll 2
    for (int hh = 0; hh < IN_; ++hh){
        float wa = WA[hh*G4c + k];
        float wb = WB[hh*G4c + k];
        ull wda = pack2(wa,wa), wdb = pack2(wb,wb);
        const ulonglong2* rp = (const ulonglong2*)&rowsT[hh*XPAD];
        #pragma unroll
        for (int p = 0; p < 4; ++p){
            ulonglong2 rv = rp[p];
            ffma2(accA[4*p],   rv.x, wda);
            ffma2(accA[4*p+1], rv.y, wda);
            ffma2(accB[4*p],   rv.x, wdb);
            ffma2(accB[4*p+1], rv.y, wdb);
        }
        const ulonglong2* rp2 = rp + 4;
        #pragma unroll
        for (int p = 0; p < 4; ++p){
            ulonglong2 rv = rp2[p];
            ffma2(accA[4*p+2], rv.x, wda);
            ffma2(accA[4*p+3], rv.y, wda);
            ffma2(accB[4*p+2], rv.x, wdb);
            ffma2(accB[4*p+3], rv.y, wdb);
        }
    }

    // accA[4p]:q(4p,4p+1)  accA[4p+1]:q(4p+2,4p+3)
    // accA[4p+2]:q(16+4p,+1)  accA[4p+3]:q(16+4p+2,+3)
    #pragma unroll
    for (int p = 0; p < 4; ++p){
        #pragma unroll
        for (int u = 0; u < 4; ++u){
            int q = (u < 2) ? (4*p + 2*u) : (16 + 4*p + 2*(u-2));
            float2 fa = unpack2(accA[4*p+u]);
            float2 fb = unpack2(accB[4*p+u]);
            int it0 = half*32 + q;
            size_t b0 = ((size_t)r*Tc + it0)*G4c + k;
            d_xg[b0]       = fa.x;
            d_xg[b0 + G4c] = fa.y;
            size_t b1 = (((size_t)Rc + r)*Tc + (Tc-1-it0))*G4c + k;
            d_xg[b1]       = fb.x;
            d_xg[b1 - G4c] = fb.y;
        }
    }
}

// ------------------------- LSTM recurrence (f32x2) -----------------------
template<bool L1>
__global__ void __launch_bounds__(256) k_rec(const float* __restrict__ Whh)
{
    int dir = blockIdx.y;
    int r0  = blockIdx.x * 4;
    int k   = threadIdx.x;
    __shared__ __align__(16) float hsm[4][Hc];
    __shared__ float gsm[4][G4c];

    ull w2[32];
    const float* Wd = Whh + dir*Hc*G4c;
    #pragma unroll
    for (int i = 0; i < 32; ++i)
        w2[i] = pack2(Wd[(2*i)*G4c + k], Wd[(2*i+1)*G4c + k]);

    hsm[k>>6][k&63] = 0.f;
    float cc = 0.f;
    const int hid = k & 63, row = k >> 6;
    __syncthreads();

    const float* xgd = d_xg + ((size_t)dir*Rc + r0)*Tc*G4c;
    for (int tau = 0; tau < Tc; ++tau){
        #pragma unroll
        for (int rr = 0; rr < 4; ++rr){
            ull a0 = pack2(xgd[((size_t)rr*Tc + tau)*G4c + k], 0.f);
            ull a1 = 0;
            const ulonglong2* hp = (const ulonglong2*)hsm[rr];
            #pragma unroll
            for (int i = 0; i < 16; ++i){
                ulonglong2 hv = hp[i];
                ffma2(a0, hv.x, w2[2*i]);
                ffma2(a1, hv.y, w2[2*i+1]);
            }
            float2 f0 = unpack2(a0), f1 = unpack2(a1);
            gsm[rr][k] = (f0.x + f1.x) + (f0.y + f1.y);
        }
        __syncthreads();
        float gi = gsm[row][hid],     gf = gsm[row][64+hid];
        float gg = gsm[row][128+hid], go = gsm[row][192+hid];
        float cn = sigfast(gf)*cc + sigfast(gi)*tanhfast(gg);
        float hn = sigfast(go)*tanhfast(cn);
        cc = cn;
        hsm[row][hid] = hn;
        if (!L1) d_hs0[((size_t)(dir*Rc + r0 + row)*Tc + tau)*Hc + hid] = hn;
        __syncthreads();
    }
    if (L1) d_hlast[(size_t)(dir*Rc + r0 + row)*Hc + hid] = hsm[row][hid];
}

// --------------------------- final FC ------------------------------------
__global__ void __launch_bounds__(128) k_fc(const float* __restrict__ fcW,
    const float* __restrict__ fcb, float* __restrict__ out)
{
    int r = blockIdx.x * blockDim.x + threadIdx.x;
    if (r >= Rc) return;
    float acc = fcb[0];
    #pragma unroll
    for (int hh = 0; hh < Hc; ++hh) acc += d_hlast[(size_t)r*Hc + hh]        * fcW[hh];
    #pragma unroll
    for (int hh = 0; hh < Hc; ++hh) acc += d_hlast[((size_t)Rc + r)*Hc + hh] * fcW[64 + hh];
    out[r] = acc;
}

// --------------------------------------------------------------------------
extern "C" void kernel_launch(void* const* d_in, const int* in_sizes, int n_in,
                              void* d_out, int out_size)
{
    const float* x       = (const float*)d_in[0];
    const float* adj     = (const float*)d_in[1];
    const float* gat0_W  = (const float*)d_in[2];
    const float* gat0_a  = (const float*)d_in[3];
    const float* gat0_g  = (const float*)d_in[4];
    const float* gat0_b  = (const float*)d_in[5];
    const float* gat1_W  = (const float*)d_in[6];
    const float* gat1_a  = (const float*)d_in[7];
    const float* gat1_g  = (const float*)d_in[8];
    const float* gat1_b  = (const float*)d_in[9];
    const float* res_W   = (const float*)d_in[10];
    const float* res_b   = (const float*)d_in[11];
    const float* alpha   = (const float*)d_in[12];
    const float* l0_Wih  = (const float*)d_in[13];
    const float* l0_Whh  = (const float*)d_in[14];
    const float* l0_bih  = (const float*)d_in[15];
    const float* l0_bhh  = (const float*)d_in[16];
    const float* l1_Wih  = (const float*)d_in[17];
    const float* l1_Whh  = (const float*)d_in[18];
    const float* l1_bih  = (const float*)d_in[19];
    const float* l1_bhh  = (const float*)d_in[20];
    const float* fc_W    = (const float*)d_in[21];
    const float* fc_b    = (const float*)d_in[22];
    float* out = (float*)d_out;

    cudaFuncSetAttribute(k_attn, cudaFuncAttributeMaxDynamicSharedMemorySize, ATTN_SMEM);

    // GAT layer 0
    k_proj<Fc, false><<<Mc*Nc/4, 256>>>(x, gat0_W, gat0_a);
    k_attn<<<dim3(Mc, 2), 256, ATTN_SMEM>>>(adj, gat0_g, gat0_b);
    // GAT layer 1
    k_proj<Hc, true><<<Mc*Nc/4, 256>>>(nullptr, gat1_W, gat1_a);
    k_attn<<<dim3(Mc, 2), 256, ATTN_SMEM>>>(adj, gat1_g, gat1_b);
    // residual combine + transpose to sequences
    k_comb<<<Mc*Nc/4, 256>>>(x, res_W, res_b, alpha);
    // BiLSTM layer 0
    k_xg<Hc,   false><<<Rc*2, 256>>>(l0_Wih, l0_bih, l0_bhh);
    k_rec<false><<<dim3(Rc/4, 2), 256>>>(l0_Whh);
    // BiLSTM layer 1
    k_xg<2*Hc, true><<<Rc*2, 256>>>(l1_Wih, l1_bih, l1_bhh);
    k_rec<true><<<dim3(Rc/4, 2), 256>>>(l1_Whh);
    // final FC
    k_fc<<<(Rc + 127)/128, 128>>>(fc_W, fc_b, out);
}

// round 10
// speedup vs baseline: 1.8202x; 1.0217x over previous
#include <cuda_runtime.h>
#include <math.h>

typedef unsigned long long ull;

#define Bc 4
#define Sc 64
#define Nc 256
#define Fc 32
#define Hc 64
#define Mc (Bc*Sc)     // 256 graphs
#define Rc (Bc*Nc)     // 1024 sequences
#define Tc Sc          // 64 timesteps
#define G4c (4*Hc)     // 256 gate columns
#define NEGV (-9e15f)

// ---------------- device scratch ----------------
__device__ float d_h[Mc*Nc*Hc];          // row-major [m][n][h]
__device__ float d_g[Mc*Nc*Hc];          // row-major [m][n][h]
__device__ float d_si[Mc*Nc];
__device__ float d_sj[Mc*Nc];
__device__ float d_seq[Rc*Tc*Hc];
__device__ float d_xg[2*Rc*Tc*G4c];
__device__ float d_hs0[2*Rc*Tc*Hc];
__device__ float d_hlast[2*Rc*Hc];

__device__ __forceinline__ float warp_sum(float v){
    #pragma unroll
    for (int o=16;o;o>>=1) v += __shfl_xor_sync(0xffffffffu, v, o);
    return v;
}
__device__ __forceinline__ float warp_max(float v){
    #pragma unroll
    for (int o=16;o;o>>=1) v = fmaxf(v, __shfl_xor_sync(0xffffffffu, v, o));
    return v;
}
__device__ __forceinline__ void ffma2(ull& acc, ull a, ull b){
    asm("fma.rn.f32x2 %0, %1, %2, %0;" : "+l"(acc) : "l"(a), "l"(b));
}
__device__ __forceinline__ ull pack2(float x, float y){
    ull r; asm("mov.b64 %0, {%1, %2};" : "=l"(r) : "f"(x), "f"(y)); return r;
}
__device__ __forceinline__ float2 unpack2(ull v){
    float2 f; asm("mov.b64 {%0, %1}, %2;" : "=f"(f.x), "=f"(f.y) : "l"(v)); return f;
}
__device__ __forceinline__ float tanhfast(float x){
    float y; asm("tanh.approx.f32 %0, %1;" : "=f"(y) : "f"(x)); return y;
}
__device__ __forceinline__ float sigfast(float x){
    return fmaf(0.5f, tanhfast(0.5f*x), 0.5f);
}

// ---------------- GAT projection: 4 rows per block ----------------
template<int FIN_, bool FROM_G>
__global__ void __launch_bounds__(256) k_proj(const float* __restrict__ X,
    const float* __restrict__ W, const float* __restrict__ a)
{
    const int t = threadIdx.x;
    const int grp = t >> 6, h = t & 63;
    const int row0 = blockIdx.x * 4;
    __shared__ float xr[4][FIN_];
    __shared__ float red2[2][4][2];      // [si|sj][grp][warp-in-grp]
    const float* src = FROM_G ? d_g : X;
    #pragma unroll
    for (int i = 0; i < (4*FIN_+255)/256; ++i){
        int idx = t + 256*i;
        if (idx < 4*FIN_){
            int rr = idx / FIN_, f = idx % FIN_;
            xr[rr][f] = src[(size_t)(row0+rr)*FIN_ + f];
        }
    }
    __syncthreads();
    float acc = 0.f;
    #pragma unroll
    for (int f = 0; f < FIN_; ++f) acc += xr[grp][f] * W[f*Hc + h];
    d_h[(size_t)(row0+grp)*Hc + h] = acc;
    float v1 = warp_sum(acc * a[h]);
    float v2 = warp_sum(acc * a[Hc + h]);
    const int wig = (t >> 5) & 1;
    if ((t & 31) == 0){ red2[0][grp][wig] = v1; red2[1][grp][wig] = v2; }
    __syncthreads();
    if (h == 0){
        d_si[row0+grp] = red2[0][grp][0] + red2[0][grp][1];
        d_sj[row0+grp] = red2[1][grp][0] + red2[1][grp][1];
    }
}

// --------- GAT attention: rr=8 rows/warp, conflict-free f32x2 ------------
#define HST 268                                     // 67 (16B units) ≡ 3 mod 8
#define ATTN_SMEM ((Hc*HST + 8*8*Nc + 2*Nc) * 4)    // ~133 KB
__global__ void __launch_bounds__(256) k_attn(const float* __restrict__ adj,
    const float* __restrict__ gamma, const float* __restrict__ beta)
{
    extern __shared__ float sm[];
    float* h_smT = sm;                    // [h=64][j], stride HST
    float* p_sm  = sm + Hc*HST;           // [8 warps][8 rows][256]
    float* si_sm = p_sm + 8*8*Nc;         // [256]
    float* sj_sm = si_sm + Nc;            // [256]

    const int m = blockIdx.x;
    const int half = blockIdx.y;          // 0: rows 0..127, 1: rows 128..255
    const int t = threadIdx.x, w = t>>5, lane = t&31;

    // transpose d_h [n][h] -> h_smT[h][n]; component rotation limits conflicts
    const float4* hg4 = (const float4*)(d_h + (size_t)m*Nc*Hc);
    #pragma unroll
    for (int i = 0; i < 16; ++i){
        int f4 = t + 256*i;
        int n  = f4 >> 4;
        int hq = f4 & 15;
        float4 v = hg4[f4];
        #pragma unroll
        for (int u = 0; u < 4; ++u){
            int c = (u + hq) & 3;
            float a0 = (c & 1) ? v.y : v.x;
            float a1 = (c & 1) ? v.w : v.z;
            float val = (c & 2) ? a1 : a0;
            h_smT[(4*hq + c)*HST + n] = val;
        }
    }
    si_sm[t] = d_si[m*Nc + t];
    sj_sm[t] = d_sj[m*Nc + t];
    __syncthreads();

    const float gm0 = gamma[lane], gm1 = gamma[lane+32];
    const float bt0 = beta[lane],  bt1 = beta[lane+32];
    float* pw = p_sm + w*(8*Nc);
    const float* hA_base = h_smT + lane*HST;
    const float* hB_base = h_smT + (lane+32)*HST;

    for (int g = 0; g < 2; ++g){
        // ---- softmax for this warp's 8 rows ----
        #pragma unroll
        for (int rr = 0; rr < 8; ++rr){
            int i = half*128 + w*16 + g*8 + rr;
            float si = si_sm[i];
            const float* arow = adj + ((size_t)m*Nc + i)*Nc;
            float ev[8]; float mx = -3.402823466e38f;
            #pragma unroll
            for (int q = 0; q < 8; ++q){
                int j = q*32 + lane;
                float e = si + sj_sm[j];
                e = e > 0.f ? e : 0.2f*e;
                if (arow[j] <= 0.f) e = NEGV;
                ev[q] = e; mx = fmaxf(mx, e);
            }
            mx = warp_max(mx);
            float s = 0.f;
            #pragma unroll
            for (int q = 0; q < 8; ++q){ ev[q] = __expf(ev[q]-mx); s += ev[q]; }
            s = warp_sum(s);
            float inv = 1.f / s;
            #pragma unroll
            for (int q = 0; q < 8; ++q) pw[rr*Nc + q*32 + lane] = ev[q]*inv;
        }
        __syncwarp();

        // ---- aggregation: packed over j pairs; lane owns cols (l, l+32) ----
        ull acc[8][2];
        #pragma unroll
        for (int rr = 0; rr < 8; ++rr){ acc[rr][0] = 0; acc[rr][1] = 0; }
        #pragma unroll 2
        for (int j0 = 0; j0 < 256; j0 += 4){
            ulonglong2 hA = *(const ulonglong2*)(hA_base + j0);
            ulonglong2 hB = *(const ulonglong2*)(hB_base + j0);
            #pragma unroll
            for (int rr = 0; rr < 8; ++rr){
                ulonglong2 pp = *(const ulonglong2*)(pw + rr*Nc + j0);
                ffma2(acc[rr][0], pp.x, hA.x);
                ffma2(acc[rr][0], pp.y, hA.y);
                ffma2(acc[rr][1], pp.x, hB.x);
                ffma2(acc[rr][1], pp.y, hB.y);
            }
        }
        __syncwarp();

        // ---- LayerNorm + ELU ----
        #pragma unroll
        for (int rr = 0; rr < 8; ++rr){
            float2 u0 = unpack2(acc[rr][0]);
            float2 u1 = unpack2(acc[rr][1]);
            float a0 = u0.x + u0.y, a1 = u1.x + u1.y;
            float s1 = warp_sum(a0 + a1);
            float s2 = warp_sum(a0*a0 + a1*a1);
            float mean = s1 * (1.f/64.f);
            float var  = s2 * (1.f/64.f) - mean*mean;
            float rstd = rsqrtf(var + 1e-5f);
            float e0 = (a0-mean)*rstd*gm0 + bt0;
            float e1 = (a1-mean)*rstd*gm1 + bt1;
            e0 = e0 > 0.f ? e0 : (__expf(e0) - 1.f);
            e1 = e1 > 0.f ? e1 : (__expf(e1) - 1.f);
            int i = half*128 + w*16 + g*8 + rr;
            d_g[((size_t)m*Nc + i)*Hc + lane]      = e0;
            d_g[((size_t)m*Nc + i)*Hc + lane + 32] = e1;
        }
    }
}

// ------- residual + gated combine + transpose (4 rows / block) -----------
__global__ void __launch_bounds__(256) k_comb(const float* __restrict__ X,
    const float* __restrict__ Wr, const float* __restrict__ br,
    const float* __restrict__ alpha)
{
    const int t = threadIdx.x;
    const int row = blockIdx.x*4 + (t>>6);
    const int h = t & 63;
    __shared__ float xr[4][Fc+1];
    if (t < 128){
        int rr = t>>5, f = t&31;
        xr[rr][f] = X[(size_t)(blockIdx.x*4 + rr)*Fc + f];
    }
    __syncthreads();
    const int rr = t>>6;
    float acc = br[h];
    #pragma unroll
    for (int f = 0; f < Fc; ++f) acc += xr[rr][f] * Wr[f*Hc + h];
    float gate = fminf(fmaxf(alpha[0], 0.f), 1.f);
    int m = row >> 8, n = row & 255;
    int b = m >> 6, s = m & 63;
    d_seq[(((size_t)b*Nc + n)*Tc + s)*Hc + h] = acc + gate * d_g[(size_t)row*Hc + h];
}

// ---------- LSTM input gates: both directions share the row tile ----------
#define XPAD 36
template<int IN_, bool L1>
__global__ void __launch_bounds__(256) k_xg(const float* __restrict__ Wih,
    const float* __restrict__ bih, const float* __restrict__ bhh)
{
    const int r    = blockIdx.x >> 1;
    const int half = blockIdx.x & 1;
    const int k    = threadIdx.x;
    __shared__ __align__(16) float rowsT[IN_*XPAD];   // [hh][q]

    #pragma unroll
    for (int i = 0; i < IN_/8; ++i){
        int idx = k + 256*i;
        int hh = idx & (IN_-1);
        int q  = idx >> (IN_==64?6:7);
        int it = half*32 + q;
        float v;
        if (!L1){
            v = d_seq[((size_t)r*Tc + it)*Hc + hh];
        } else {
            if (hh < 64) v = d_hs0[((size_t)r*Tc + it)*Hc + hh];
            else         v = d_hs0[(((size_t)Rc + r)*Tc + (Tc-1-it))*Hc + (hh-64)];
        }
        rowsT[hh*XPAD + q] = v;
    }
    __syncthreads();

    const float* WA = Wih;
    const float* WB = Wih + IN_*G4c;
    float bvA = bih[k] + bhh[k];
    float bvB = bih[G4c + k] + bhh[G4c + k];
    ull accA[16], accB[16];
    #pragma unroll
    for (int i = 0; i < 16; ++i){ accA[i] = pack2(bvA,bvA); accB[i] = pack2(bvB,bvB); }

    #pragma unroll 2
    for (int hh = 0; hh < IN_; ++hh){
        float wa = WA[hh*G4c + k];
        float wb = WB[hh*G4c + k];
        ull wda = pack2(wa,wa), wdb = pack2(wb,wb);
        const ulonglong2* rp = (const ulonglong2*)&rowsT[hh*XPAD];
        #pragma unroll
        for (int p = 0; p < 4; ++p){
            ulonglong2 rv = rp[p];
            ffma2(accA[4*p],   rv.x, wda);
            ffma2(accA[4*p+1], rv.y, wda);
            ffma2(accB[4*p],   rv.x, wdb);
            ffma2(accB[4*p+1], rv.y, wdb);
        }
        const ulonglong2* rp2 = rp + 4;
        #pragma unroll
        for (int p = 0; p < 4; ++p){
            ulonglong2 rv = rp2[p];
            ffma2(accA[4*p+2], rv.x, wda);
            ffma2(accA[4*p+3], rv.y, wda);
            ffma2(accB[4*p+2], rv.x, wdb);
            ffma2(accB[4*p+3], rv.y, wdb);
        }
    }

    // accA[4p]:q(4p,4p+1)  accA[4p+1]:q(4p+2,4p+3)
    // accA[4p+2]:q(16+4p,+1)  accA[4p+3]:q(16+4p+2,+3)
    #pragma unroll
    for (int p = 0; p < 4; ++p){
        #pragma unroll
        for (int u = 0; u < 4; ++u){
            int q = (u < 2) ? (4*p + 2*u) : (16 + 4*p + 2*(u-2));
            float2 fa = unpack2(accA[4*p+u]);
            float2 fb = unpack2(accB[4*p+u]);
            int it0 = half*32 + q;
            size_t b0 = ((size_t)r*Tc + it0)*G4c + k;
            d_xg[b0]       = fa.x;
            d_xg[b0 + G4c] = fa.y;
            size_t b1 = (((size_t)Rc + r)*Tc + (Tc-1-it0))*G4c + k;
            d_xg[b1]       = fb.x;
            d_xg[b1 - G4c] = fb.y;
        }
    }
}

// ------------------ LSTM recurrence (f32x2, 8 seqs/block) ----------------
// Thread k holds Whh column k (32 f32x2 pairs); owns hidden unit k&63 of
// rows rA=k>>6 and rB=4+(k>>6). xg prefetched 8-wide per step.
template<bool L1>
__global__ void __launch_bounds__(256) k_rec(const float* __restrict__ Whh)
{
    int dir = blockIdx.y;
    int r0  = blockIdx.x * 8;
    int k   = threadIdx.x;
    __shared__ __align__(16) float hsm[8][Hc];
    __shared__ float gsm[8][G4c];

    ull w2[32];
    const float* Wd = Whh + dir*Hc*G4c;
    #pragma unroll
    for (int i = 0; i < 32; ++i)
        w2[i] = pack2(Wd[(2*i)*G4c + k], Wd[(2*i+1)*G4c + k]);

    const int hid = k & 63, rA = k >> 6, rB = 4 + (k >> 6);
    hsm[rA][hid] = 0.f;
    hsm[rB][hid] = 0.f;
    float cc0 = 0.f, cc1 = 0.f;
    __syncthreads();

    const float* xgd = d_xg + ((size_t)dir*Rc + r0)*Tc*G4c;
    for (int tau = 0; tau < Tc; ++tau){
        float xv[8];
        #pragma unroll
        for (int rr = 0; rr < 8; ++rr)
            xv[rr] = xgd[((size_t)rr*Tc + tau)*G4c + k];
        #pragma unroll
        for (int rr = 0; rr < 8; ++rr){
            ull a0 = pack2(xv[rr], 0.f);
            ull a1 = 0;
            const ulonglong2* hp = (const ulonglong2*)hsm[rr];
            #pragma unroll
            for (int i = 0; i < 16; ++i){
                ulonglong2 hv = hp[i];
                ffma2(a0, hv.x, w2[2*i]);
                ffma2(a1, hv.y, w2[2*i+1]);
            }
            float2 f0 = unpack2(a0), f1 = unpack2(a1);
            gsm[rr][k] = (f0.x + f1.x) + (f0.y + f1.y);
        }
        __syncthreads();
        {
            float gi = gsm[rA][hid],     gf = gsm[rA][64+hid];
            float gg = gsm[rA][128+hid], go = gsm[rA][192+hid];
            float cn = sigfast(gf)*cc0 + sigfast(gi)*tanhfast(gg);
            float hn = sigfast(go)*tanhfast(cn);
            cc0 = cn; hsm[rA][hid] = hn;
            if (!L1) d_hs0[((size_t)(dir*Rc + r0 + rA)*Tc + tau)*Hc + hid] = hn;
        }
        {
            float gi = gsm[rB][hid],     gf = gsm[rB][64+hid];
            float gg = gsm[rB][128+hid], go = gsm[rB][192+hid];
            float cn = sigfast(gf)*cc1 + sigfast(gi)*tanhfast(gg);
            float hn = sigfast(go)*tanhfast(cn);
            cc1 = cn; hsm[rB][hid] = hn;
            if (!L1) d_hs0[((size_t)(dir*Rc + r0 + rB)*Tc + tau)*Hc + hid] = hn;
        }
        __syncthreads();
    }
    if (L1){
        d_hlast[(size_t)(dir*Rc + r0 + rA)*Hc + hid] = hsm[rA][hid];
        d_hlast[(size_t)(dir*Rc + r0 + rB)*Hc + hid] = hsm[rB][hid];
    }
}

// --------------------------- final FC ------------------------------------
__global__ void __launch_bounds__(128) k_fc(const float* __restrict__ fcW,
    const float* __restrict__ fcb, float* __restrict__ out)
{
    int r = blockIdx.x * blockDim.x + threadIdx.x;
    if (r >= Rc) return;
    float acc = fcb[0];
    #pragma unroll
    for (int hh = 0; hh < Hc; ++hh) acc += d_hlast[(size_t)r*Hc + hh]        * fcW[hh];
    #pragma unroll
    for (int hh = 0; hh < Hc; ++hh) acc += d_hlast[((size_t)Rc + r)*Hc + hh] * fcW[64 + hh];
    out[r] = acc;
}

// --------------------------------------------------------------------------
extern "C" void kernel_launch(void* const* d_in, const int* in_sizes, int n_in,
                              void* d_out, int out_size)
{
    const float* x       = (const float*)d_in[0];
    const float* adj     = (const float*)d_in[1];
    const float* gat0_W  = (const float*)d_in[2];
    const float* gat0_a  = (const float*)d_in[3];
    const float* gat0_g  = (const float*)d_in[4];
    const float* gat0_b  = (const float*)d_in[5];
    const float* gat1_W  = (const float*)d_in[6];
    const float* gat1_a  = (const float*)d_in[7];
    const float* gat1_g  = (const float*)d_in[8];
    const float* gat1_b  = (const float*)d_in[9];
    const float* res_W   = (const float*)d_in[10];
    const float* res_b   = (const float*)d_in[11];
    const float* alpha   = (const float*)d_in[12];
    const float* l0_Wih  = (const float*)d_in[13];
    const float* l0_Whh  = (const float*)d_in[14];
    const float* l0_bih  = (const float*)d_in[15];
    const float* l0_bhh  = (const float*)d_in[16];
    const float* l1_Wih  = (const float*)d_in[17];
    const float* l1_Whh  = (const float*)d_in[18];
    const float* l1_bih  = (const float*)d_in[19];
    const float* l1_bhh  = (const float*)d_in[20];
    const float* fc_W    = (const float*)d_in[21];
    const float* fc_b    = (const float*)d_in[22];
    float* out = (float*)d_out;

    cudaFuncSetAttribute(k_attn, cudaFuncAttributeMaxDynamicSharedMemorySize, ATTN_SMEM);

    // GAT layer 0
    k_proj<Fc, false><<<Mc*Nc/4, 256>>>(x, gat0_W, gat0_a);
    k_attn<<<dim3(Mc, 2), 256, ATTN_SMEM>>>(adj, gat0_g, gat0_b);
    // GAT layer 1
    k_proj<Hc, true><<<Mc*Nc/4, 256>>>(nullptr, gat1_W, gat1_a);
    k_attn<<<dim3(Mc, 2), 256, ATTN_SMEM>>>(adj, gat1_g, gat1_b);
    // residual combine + transpose to sequences
    k_comb<<<Mc*Nc/4, 256>>>(x, res_W, res_b, alpha);
    // BiLSTM layer 0
    k_xg<Hc,   false><<<Rc*2, 256>>>(l0_Wih, l0_bih, l0_bhh);
    k_rec<false><<<dim3(Rc/8, 2), 256>>>(l0_Whh);
    // BiLSTM layer 1
    k_xg<2*Hc, true><<<Rc*2, 256>>>(l1_Wih, l1_bih, l1_bhh);
    k_rec<true><<<dim3(Rc/8, 2), 256>>>(l1_Whh);
    // final FC
    k_fc<<<(Rc + 127)/128, 128>>>(fc_W, fc_b, out);
}

// round 11
// speedup vs baseline: 1.9108x; 1.0498x over previous
#include <cuda_runtime.h>
#include <math.h>

typedef unsigned long long ull;

#define Bc 4
#define Sc 64
#define Nc 256
#define Fc 32
#define Hc 64
#define Mc (Bc*Sc)     // 256 graphs
#define Rc (Bc*Nc)     // 1024 sequences
#define Tc Sc          // 64 timesteps
#define G4c (4*Hc)     // 256 gate columns
#define NEGV (-9e15f)

// ---------------- device scratch ----------------
__device__ float d_h[Mc*Nc*Hc];          // row-major [m][n][h]
__device__ float d_g[Mc*Nc*Hc];          // row-major [m][n][h]
__device__ float d_si[Mc*Nc];
__device__ float d_sj[Mc*Nc];
__device__ float d_seq[Rc*Tc*Hc];
__device__ float d_xg[2*Rc*Tc*G4c];
__device__ float d_hs0[2*Rc*Tc*Hc];
__device__ float d_hlast[2*Rc*Hc];

__device__ __forceinline__ float warp_sum(float v){
    #pragma unroll
    for (int o=16;o;o>>=1) v += __shfl_xor_sync(0xffffffffu, v, o);
    return v;
}
__device__ __forceinline__ float warp_max(float v){
    #pragma unroll
    for (int o=16;o;o>>=1) v = fmaxf(v, __shfl_xor_sync(0xffffffffu, v, o));
    return v;
}
__device__ __forceinline__ void ffma2(ull& acc, ull a, ull b){
    asm("fma.rn.f32x2 %0, %1, %2, %0;" : "+l"(acc) : "l"(a), "l"(b));
}
__device__ __forceinline__ ull pack2(float x, float y){
    ull r; asm("mov.b64 %0, {%1, %2};" : "=l"(r) : "f"(x), "f"(y)); return r;
}
__device__ __forceinline__ float2 unpack2(ull v){
    float2 f; asm("mov.b64 {%0, %1}, %2;" : "=f"(f.x), "=f"(f.y) : "l"(v)); return f;
}
__device__ __forceinline__ float tanhfast(float x){
    float y; asm("tanh.approx.f32 %0, %1;" : "=f"(y) : "f"(x)); return y;
}
__device__ __forceinline__ float sigfast(float x){
    return fmaf(0.5f, tanhfast(0.5f*x), 0.5f);
}

// ---------------- GAT projection: 4 rows per block ----------------
template<int FIN_, bool FROM_G>
__global__ void __launch_bounds__(256) k_proj(const float* __restrict__ X,
    const float* __restrict__ W, const float* __restrict__ a)
{
    const int t = threadIdx.x;
    const int grp = t >> 6, h = t & 63;
    const int row0 = blockIdx.x * 4;
    __shared__ float xr[4][FIN_];
    __shared__ float red2[2][4][2];      // [si|sj][grp][warp-in-grp]
    const float* src = FROM_G ? d_g : X;
    #pragma unroll
    for (int i = 0; i < (4*FIN_+255)/256; ++i){
        int idx = t + 256*i;
        if (idx < 4*FIN_){
            int rr = idx / FIN_, f = idx % FIN_;
            xr[rr][f] = src[(size_t)(row0+rr)*FIN_ + f];
        }
    }
    __syncthreads();
    float acc = 0.f;
    #pragma unroll
    for (int f = 0; f < FIN_; ++f) acc += xr[grp][f] * W[f*Hc + h];
    d_h[(size_t)(row0+grp)*Hc + h] = acc;
    float v1 = warp_sum(acc * a[h]);
    float v2 = warp_sum(acc * a[Hc + h]);
    const int wig = (t >> 5) & 1;
    if ((t & 31) == 0){ red2[0][grp][wig] = v1; red2[1][grp][wig] = v2; }
    __syncthreads();
    if (h == 0){
        d_si[row0+grp] = red2[0][grp][0] + red2[0][grp][1];
        d_sj[row0+grp] = red2[1][grp][0] + red2[1][grp][1];
    }
}

// --------- GAT attention: rr=4 rows/warp (R9-proven), f32x2 --------------
#define HST 268                                     // 67 (16B units) ≡ 3 mod 8
#define ATTN_SMEM ((Hc*HST + 8*4*Nc + 2*Nc) * 4)    // ~101 KB → 2 blocks/SM
__global__ void __launch_bounds__(256) k_attn(const float* __restrict__ adj,
    const float* __restrict__ gamma, const float* __restrict__ beta)
{
    extern __shared__ float sm[];
    float* h_smT = sm;                    // [h=64][j], stride HST
    float* p_sm  = sm + Hc*HST;           // [8 warps][4 rows][256]
    float* si_sm = p_sm + 8*4*Nc;         // [256]
    float* sj_sm = si_sm + Nc;            // [256]

    const int m = blockIdx.x;
    const int half = blockIdx.y;          // 0: rows 0..127, 1: rows 128..255
    const int t = threadIdx.x, w = t>>5, lane = t&31;

    // transpose d_h [n][h] -> h_smT[h][n]; component rotation limits conflicts
    const float4* hg4 = (const float4*)(d_h + (size_t)m*Nc*Hc);
    #pragma unroll
    for (int i = 0; i < 16; ++i){
        int f4 = t + 256*i;
        int n  = f4 >> 4;
        int hq = f4 & 15;
        float4 v = hg4[f4];
        #pragma unroll
        for (int u = 0; u < 4; ++u){
            int c = (u + hq) & 3;
            float a0 = (c & 1) ? v.y : v.x;
            float a1 = (c & 1) ? v.w : v.z;
            float val = (c & 2) ? a1 : a0;
            h_smT[(4*hq + c)*HST + n] = val;
        }
    }
    si_sm[t] = d_si[m*Nc + t];
    sj_sm[t] = d_sj[m*Nc + t];
    __syncthreads();

    const float gm0 = gamma[lane], gm1 = gamma[lane+32];
    const float bt0 = beta[lane],  bt1 = beta[lane+32];
    float* pw = p_sm + w*(4*Nc);
    const float* hA_base = h_smT + lane*HST;
    const float* hB_base = h_smT + (lane+32)*HST;

    for (int g = 0; g < 4; ++g){
        // ---- softmax for this warp's 4 rows ----
        #pragma unroll
        for (int rr = 0; rr < 4; ++rr){
            int i = half*128 + w*16 + g*4 + rr;
            float si = si_sm[i];
            const float* arow = adj + ((size_t)m*Nc + i)*Nc;
            float ev[8]; float mx = -3.402823466e38f;
            #pragma unroll
            for (int q = 0; q < 8; ++q){
                int j = q*32 + lane;
                float e = si + sj_sm[j];
                e = e > 0.f ? e : 0.2f*e;
                if (arow[j] <= 0.f) e = NEGV;
                ev[q] = e; mx = fmaxf(mx, e);
            }
            mx = warp_max(mx);
            float s = 0.f;
            #pragma unroll
            for (int q = 0; q < 8; ++q){ ev[q] = __expf(ev[q]-mx); s += ev[q]; }
            s = warp_sum(s);
            float inv = 1.f / s;
            #pragma unroll
            for (int q = 0; q < 8; ++q) pw[rr*Nc + q*32 + lane] = ev[q]*inv;
        }
        __syncwarp();

        // ---- aggregation: packed over j pairs; lane owns cols (l, l+32) ----
        ull acc[4][2];
        #pragma unroll
        for (int rr = 0; rr < 4; ++rr){ acc[rr][0] = 0; acc[rr][1] = 0; }
        #pragma unroll 4
        for (int j0 = 0; j0 < 256; j0 += 4){
            ulonglong2 hA = *(const ulonglong2*)(hA_base + j0);
            ulonglong2 hB = *(const ulonglong2*)(hB_base + j0);
            #pragma unroll
            for (int rr = 0; rr < 4; ++rr){
                ulonglong2 pp = *(const ulonglong2*)(pw + rr*Nc + j0);
                ffma2(acc[rr][0], pp.x, hA.x);
                ffma2(acc[rr][0], pp.y, hA.y);
                ffma2(acc[rr][1], pp.x, hB.x);
                ffma2(acc[rr][1], pp.y, hB.y);
            }
        }
        __syncwarp();

        // ---- LayerNorm + ELU ----
        #pragma unroll
        for (int rr = 0; rr < 4; ++rr){
            float2 u0 = unpack2(acc[rr][0]);
            float2 u1 = unpack2(acc[rr][1]);
            float a0 = u0.x + u0.y, a1 = u1.x + u1.y;
            float s1 = warp_sum(a0 + a1);
            float s2 = warp_sum(a0*a0 + a1*a1);
            float mean = s1 * (1.f/64.f);
            float var  = s2 * (1.f/64.f) - mean*mean;
            float rstd = rsqrtf(var + 1e-5f);
            float e0 = (a0-mean)*rstd*gm0 + bt0;
            float e1 = (a1-mean)*rstd*gm1 + bt1;
            e0 = e0 > 0.f ? e0 : (__expf(e0) - 1.f);
            e1 = e1 > 0.f ? e1 : (__expf(e1) - 1.f);
            int i = half*128 + w*16 + g*4 + rr;
            d_g[((size_t)m*Nc + i)*Hc + lane]      = e0;
            d_g[((size_t)m*Nc + i)*Hc + lane + 32] = e1;
        }
    }
}

// ------- residual + gated combine + transpose (4 rows / block) -----------
__global__ void __launch_bounds__(256) k_comb(const float* __restrict__ X,
    const float* __restrict__ Wr, const float* __restrict__ br,
    const float* __restrict__ alpha)
{
    const int t = threadIdx.x;
    const int row = blockIdx.x*4 + (t>>6);
    const int h = t & 63;
    __shared__ float xr[4][Fc+1];
    if (t < 128){
        int rr = t>>5, f = t&31;
        xr[rr][f] = X[(size_t)(blockIdx.x*4 + rr)*Fc + f];
    }
    __syncthreads();
    const int rr = t>>6;
    float acc = br[h];
    #pragma unroll
    for (int f = 0; f < Fc; ++f) acc += xr[rr][f] * Wr[f*Hc + h];
    float gate = fminf(fmaxf(alpha[0], 0.f), 1.f);
    int m = row >> 8, n = row & 255;
    int b = m >> 6, s = m & 63;
    d_seq[(((size_t)b*Nc + n)*Tc + s)*Hc + h] = acc + gate * d_g[(size_t)row*Hc + h];
}

// ---------- LSTM input gates: both directions share the row tile ----------
#define XPAD 36
template<int IN_, bool L1>
__global__ void __launch_bounds__(256) k_xg(const float* __restrict__ Wih,
    const float* __restrict__ bih, const float* __restrict__ bhh)
{
    const int r    = blockIdx.x >> 1;
    const int half = blockIdx.x & 1;
    const int k    = threadIdx.x;
    __shared__ __align__(16) float rowsT[IN_*XPAD];   // [hh][q]

    #pragma unroll
    for (int i = 0; i < IN_/8; ++i){
        int idx = k + 256*i;
        int hh = idx & (IN_-1);
        int q  = idx >> (IN_==64?6:7);
        int it = half*32 + q;
        float v;
        if (!L1){
            v = d_seq[((size_t)r*Tc + it)*Hc + hh];
        } else {
            if (hh < 64) v = d_hs0[((size_t)r*Tc + it)*Hc + hh];
            else         v = d_hs0[(((size_t)Rc + r)*Tc + (Tc-1-it))*Hc + (hh-64)];
        }
        rowsT[hh*XPAD + q] = v;
    }
    __syncthreads();

    const float* WA = Wih;
    const float* WB = Wih + IN_*G4c;
    float bvA = bih[k] + bhh[k];
    float bvB = bih[G4c + k] + bhh[G4c + k];
    ull accA[16], accB[16];
    #pragma unroll
    for (int i = 0; i < 16; ++i){ accA[i] = pack2(bvA,bvA); accB[i] = pack2(bvB,bvB); }

    #pragma unroll 2
    for (int hh = 0; hh < IN_; ++hh){
        float wa = WA[hh*G4c + k];
        float wb = WB[hh*G4c + k];
        ull wda = pack2(wa,wa), wdb = pack2(wb,wb);
        const ulonglong2* rp = (const ulonglong2*)&rowsT[hh*XPAD];
        #pragma unroll
        for (int p = 0; p < 4; ++p){
            ulonglong2 rv = rp[p];
            ffma2(accA[4*p],   rv.x, wda);
            ffma2(accA[4*p+1], rv.y, wda);
            ffma2(accB[4*p],   rv.x, wdb);
            ffma2(accB[4*p+1], rv.y, wdb);
        }
        const ulonglong2* rp2 = rp + 4;
        #pragma unroll
        for (int p = 0; p < 4; ++p){
            ulonglong2 rv = rp2[p];
            ffma2(accA[4*p+2], rv.x, wda);
            ffma2(accA[4*p+3], rv.y, wda);
            ffma2(accB[4*p+2], rv.x, wdb);
            ffma2(accB[4*p+3], rv.y, wdb);
        }
    }

    // accA[4p]:q(4p,4p+1)  accA[4p+1]:q(4p+2,4p+3)
    // accA[4p+2]:q(16+4p,+1)  accA[4p+3]:q(16+4p+2,+3)
    #pragma unroll
    for (int p = 0; p < 4; ++p){
        #pragma unroll
        for (int u = 0; u < 4; ++u){
            int q = (u < 2) ? (4*p + 2*u) : (16 + 4*p + 2*(u-2));
            float2 fa = unpack2(accA[4*p+u]);
            float2 fb = unpack2(accB[4*p+u]);
            int it0 = half*32 + q;
            size_t b0 = ((size_t)r*Tc + it0)*G4c + k;
            d_xg[b0]       = fa.x;
            d_xg[b0 + G4c] = fa.y;
            size_t b1 = (((size_t)Rc + r)*Tc + (Tc-1-it0))*G4c + k;
            d_xg[b1]       = fb.x;
            d_xg[b1 - G4c] = fb.y;
        }
    }
}

// ------------------ LSTM recurrence (f32x2, 8 seqs/block) ----------------
template<bool L1>
__global__ void __launch_bounds__(256) k_rec(const float* __restrict__ Whh)
{
    int dir = blockIdx.y;
    int r0  = blockIdx.x * 8;
    int k   = threadIdx.x;
    __shared__ __align__(16) float hsm[8][Hc];
    __shared__ float gsm[8][G4c];

    ull w2[32];
    const float* Wd = Whh + dir*Hc*G4c;
    #pragma unroll
    for (int i = 0; i < 32; ++i)
        w2[i] = pack2(Wd[(2*i)*G4c + k], Wd[(2*i+1)*G4c + k]);

    const int hid = k & 63, rA = k >> 6, rB = 4 + (k >> 6);
    hsm[rA][hid] = 0.f;
    hsm[rB][hid] = 0.f;
    float cc0 = 0.f, cc1 = 0.f;
    __syncthreads();

    const float* xgd = d_xg + ((size_t)dir*Rc + r0)*Tc*G4c;
    for (int tau = 0; tau < Tc; ++tau){
        float xv[8];
        #pragma unroll
        for (int rr = 0; rr < 8; ++rr)
            xv[rr] = xgd[((size_t)rr*Tc + tau)*G4c + k];
        #pragma unroll
        for (int rr = 0; rr < 8; ++rr){
            ull a0 = pack2(xv[rr], 0.f);
            ull a1 = 0;
            const ulonglong2* hp = (const ulonglong2*)hsm[rr];
            #pragma unroll
            for (int i = 0; i < 16; ++i){
                ulonglong2 hv = hp[i];
                ffma2(a0, hv.x, w2[2*i]);
                ffma2(a1, hv.y, w2[2*i+1]);
            }
            float2 f0 = unpack2(a0), f1 = unpack2(a1);
            gsm[rr][k] = (f0.x + f1.x) + (f0.y + f1.y);
        }
        __syncthreads();
        {
            float gi = gsm[rA][hid],     gf = gsm[rA][64+hid];
            float gg = gsm[rA][128+hid], go = gsm[rA][192+hid];
            float cn = sigfast(gf)*cc0 + sigfast(gi)*tanhfast(gg);
            float hn = sigfast(go)*tanhfast(cn);
            cc0 = cn; hsm[rA][hid] = hn;
            if (!L1) d_hs0[((size_t)(dir*Rc + r0 + rA)*Tc + tau)*Hc + hid] = hn;
        }
        {
            float gi = gsm[rB][hid],     gf = gsm[rB][64+hid];
            float gg = gsm[rB][128+hid], go = gsm[rB][192+hid];
            float cn = sigfast(gf)*cc1 + sigfast(gi)*tanhfast(gg);
            float hn = sigfast(go)*tanhfast(cn);
            cc1 = cn; hsm[rB][hid] = hn;
            if (!L1) d_hs0[((size_t)(dir*Rc + r0 + rB)*Tc + tau)*Hc + hid] = hn;
        }
        __syncthreads();
    }
    if (L1){
        d_hlast[(size_t)(dir*Rc + r0 + rA)*Hc + hid] = hsm[rA][hid];
        d_hlast[(size_t)(dir*Rc + r0 + rB)*Hc + hid] = hsm[rB][hid];
    }
}

// --------------------------- final FC ------------------------------------
__global__ void __launch_bounds__(128) k_fc(const float* __restrict__ fcW,
    const float* __restrict__ fcb, float* __restrict__ out)
{
    int r = blockIdx.x * blockDim.x + threadIdx.x;
    if (r >= Rc) return;
    float acc = fcb[0];
    #pragma unroll
    for (int hh = 0; hh < Hc; ++hh) acc += d_hlast[(size_t)r*Hc + hh]        * fcW[hh];
    #pragma unroll
    for (int hh = 0; hh < Hc; ++hh) acc += d_hlast[((size_t)Rc + r)*Hc + hh] * fcW[64 + hh];
    out[r] = acc;
}

// --------------------------------------------------------------------------
extern "C" void kernel_launch(void* const* d_in, const int* in_sizes, int n_in,
                              void* d_out, int out_size)
{
    const float* x       = (const float*)d_in[0];
    const float* adj     = (const float*)d_in[1];
    const float* gat0_W  = (const float*)d_in[2];
    const float* gat0_a  = (const float*)d_in[3];
    const float* gat0_g  = (const float*)d_in[4];
    const float* gat0_b  = (const float*)d_in[5];
    const float* gat1_W  = (const float*)d_in[6];
    const float* gat1_a  = (const float*)d_in[7];
    const float* gat1_g  = (const float*)d_in[8];
    const float* gat1_b  = (const float*)d_in[9];
    const float* res_W   = (const float*)d_in[10];
    const float* res_b   = (const float*)d_in[11];
    const float* alpha   = (const float*)d_in[12];
    const float* l0_Wih  = (const float*)d_in[13];
    const float* l0_Whh  = (const float*)d_in[14];
    const float* l0_bih  = (const float*)d_in[15];
    const float* l0_bhh  = (const float*)d_in[16];
    const float* l1_Wih  = (const float*)d_in[17];
    const float* l1_Whh  = (const float*)d_in[18];
    const float* l1_bih  = (const float*)d_in[19];
    const float* l1_bhh  = (const float*)d_in[20];
    const float* fc_W    = (const float*)d_in[21];
    const float* fc_b    = (const float*)d_in[22];
    float* out = (float*)d_out;

    cudaFuncSetAttribute(k_attn, cudaFuncAttributeMaxDynamicSharedMemorySize, ATTN_SMEM);

    // GAT layer 0
    k_proj<Fc, false><<<Mc*Nc/4, 256>>>(x, gat0_W, gat0_a);
    k_attn<<<dim3(Mc, 2), 256, ATTN_SMEM>>>(adj, gat0_g, gat0_b);
    // GAT layer 1
    k_proj<Hc, true><<<Mc*Nc/4, 256>>>(nullptr, gat1_W, gat1_a);
    k_attn<<<dim3(Mc, 2), 256, ATTN_SMEM>>>(adj, gat1_g, gat1_b);
    // residual combine + transpose to sequences
    k_comb<<<Mc*Nc/4, 256>>>(x, res_W, res_b, alpha);
    // BiLSTM layer 0
    k_xg<Hc,   false><<<Rc*2, 256>>>(l0_Wih, l0_bih, l0_bhh);
    k_rec<false><<<dim3(Rc/8, 2), 256>>>(l0_Whh);
    // BiLSTM layer 1
    k_xg<2*Hc, true><<<Rc*2, 256>>>(l1_Wih, l1_bih, l1_bhh);
    k_rec<true><<<dim3(Rc/8, 2), 256>>>(l1_Whh);
    // final FC
    k_fc<<<(Rc + 127)/128, 128>>>(fc_W, fc_b, out);
}

// round 12
// speedup vs baseline: 1.9140x; 1.0017x over previous
#include <cuda_runtime.h>
#include <math.h>

typedef unsigned long long ull;

#define Bc 4
#define Sc 64
#define Nc 256
#define Fc 32
#define Hc 64
#define Mc (Bc*Sc)     // 256 graphs
#define Rc (Bc*Nc)     // 1024 sequences
#define Tc Sc          // 64 timesteps
#define G4c (4*Hc)     // 256 gate columns
#define NEGV (-9e15f)

// ---------------- device scratch ----------------
__device__ float d_h[Mc*Nc*Hc];          // row-major [m][n][h]
__device__ float d_g[Mc*Nc*Hc];          // row-major [m][n][h]
__device__ float d_si[Mc*Nc];
__device__ float d_sj[Mc*Nc];
__device__ float d_seq[Rc*Tc*Hc];
__device__ float d_xg[2*Rc*Tc*G4c];
__device__ float d_hs0[2*Rc*Tc*Hc];
__device__ float d_hlast[2*Rc*Hc];

__device__ __forceinline__ float warp_sum(float v){
    #pragma unroll
    for (int o=16;o;o>>=1) v += __shfl_xor_sync(0xffffffffu, v, o);
    return v;
}
__device__ __forceinline__ float warp_max(float v){
    #pragma unroll
    for (int o=16;o;o>>=1) v = fmaxf(v, __shfl_xor_sync(0xffffffffu, v, o));
    return v;
}
__device__ __forceinline__ void ffma2(ull& acc, ull a, ull b){
    asm("fma.rn.f32x2 %0, %1, %2, %0;" : "+l"(acc) : "l"(a), "l"(b));
}
__device__ __forceinline__ ull pack2(float x, float y){
    ull r; asm("mov.b64 %0, {%1, %2};" : "=l"(r) : "f"(x), "f"(y)); return r;
}
__device__ __forceinline__ float2 unpack2(ull v){
    float2 f; asm("mov.b64 {%0, %1}, %2;" : "=f"(f.x), "=f"(f.y) : "l"(v)); return f;
}
__device__ __forceinline__ float tanhfast(float x){
    float y; asm("tanh.approx.f32 %0, %1;" : "=f"(y) : "f"(x)); return y;
}
__device__ __forceinline__ float sigfast(float x){
    return fmaf(0.5f, tanhfast(0.5f*x), 0.5f);
}

// ---------------- GAT projection: 4 rows per block ----------------
template<int FIN_, bool FROM_G>
__global__ void __launch_bounds__(256) k_proj(const float* __restrict__ X,
    const float* __restrict__ W, const float* __restrict__ a)
{
    const int t = threadIdx.x;
    const int grp = t >> 6, h = t & 63;
    const int row0 = blockIdx.x * 4;
    __shared__ float xr[4][FIN_];
    __shared__ float red2[2][4][2];      // [si|sj][grp][warp-in-grp]
    const float* src = FROM_G ? d_g : X;
    #pragma unroll
    for (int i = 0; i < (4*FIN_+255)/256; ++i){
        int idx = t + 256*i;
        if (idx < 4*FIN_){
            int rr = idx / FIN_, f = idx % FIN_;
            xr[rr][f] = src[(size_t)(row0+rr)*FIN_ + f];
        }
    }
    __syncthreads();
    float acc = 0.f;
    #pragma unroll
    for (int f = 0; f < FIN_; ++f) acc += xr[grp][f] * W[f*Hc + h];
    d_h[(size_t)(row0+grp)*Hc + h] = acc;
    float v1 = warp_sum(acc * a[h]);
    float v2 = warp_sum(acc * a[Hc + h]);
    const int wig = (t >> 5) & 1;
    if ((t & 31) == 0){ red2[0][grp][wig] = v1; red2[1][grp][wig] = v2; }
    __syncthreads();
    if (h == 0){
        d_si[row0+grp] = red2[0][grp][0] + red2[0][grp][1];
        d_sj[row0+grp] = red2[1][grp][0] + red2[1][grp][1];
    }
}

// --------- GAT attention: rr=4 rows/warp (R9-proven), f32x2 --------------
#define HST 268                                     // 67 (16B units) ≡ 3 mod 8
#define ATTN_SMEM ((Hc*HST + 8*4*Nc + 2*Nc) * 4)    // ~101 KB → 2 blocks/SM
__global__ void __launch_bounds__(256) k_attn(const float* __restrict__ adj,
    const float* __restrict__ gamma, const float* __restrict__ beta)
{
    extern __shared__ float sm[];
    float* h_smT = sm;                    // [h=64][j], stride HST
    float* p_sm  = sm + Hc*HST;           // [8 warps][4 rows][256]
    float* si_sm = p_sm + 8*4*Nc;         // [256]
    float* sj_sm = si_sm + Nc;            // [256]

    const int m = blockIdx.x;
    const int half = blockIdx.y;          // 0: rows 0..127, 1: rows 128..255
    const int t = threadIdx.x, w = t>>5, lane = t&31;

    // transpose d_h [n][h] -> h_smT[h][n]; component rotation limits conflicts
    const float4* hg4 = (const float4*)(d_h + (size_t)m*Nc*Hc);
    #pragma unroll
    for (int i = 0; i < 16; ++i){
        int f4 = t + 256*i;
        int n  = f4 >> 4;
        int hq = f4 & 15;
        float4 v = hg4[f4];
        #pragma unroll
        for (int u = 0; u < 4; ++u){
            int c = (u + hq) & 3;
            float a0 = (c & 1) ? v.y : v.x;
            float a1 = (c & 1) ? v.w : v.z;
            float val = (c & 2) ? a1 : a0;
            h_smT[(4*hq + c)*HST + n] = val;
        }
    }
    si_sm[t] = d_si[m*Nc + t];
    sj_sm[t] = d_sj[m*Nc + t];
    __syncthreads();

    const float gm0 = gamma[lane], gm1 = gamma[lane+32];
    const float bt0 = beta[lane],  bt1 = beta[lane+32];
    float* pw = p_sm + w*(4*Nc);
    const float* hA_base = h_smT + lane*HST;
    const float* hB_base = h_smT + (lane+32)*HST;

    for (int g = 0; g < 4; ++g){
        // ---- softmax for this warp's 4 rows ----
        #pragma unroll
        for (int rr = 0; rr < 4; ++rr){
            int i = half*128 + w*16 + g*4 + rr;
            float si = si_sm[i];
            const float* arow = adj + ((size_t)m*Nc + i)*Nc;
            float ev[8]; float mx = -3.402823466e38f;
            #pragma unroll
            for (int q = 0; q < 8; ++q){
                int j = q*32 + lane;
                float e = si + sj_sm[j];
                e = e > 0.f ? e : 0.2f*e;
                if (arow[j] <= 0.f) e = NEGV;
                ev[q] = e; mx = fmaxf(mx, e);
            }
            mx = warp_max(mx);
            float s = 0.f;
            #pragma unroll
            for (int q = 0; q < 8; ++q){ ev[q] = __expf(ev[q]-mx); s += ev[q]; }
            s = warp_sum(s);
            float inv = 1.f / s;
            #pragma unroll
            for (int q = 0; q < 8; ++q) pw[rr*Nc + q*32 + lane] = ev[q]*inv;
        }
        __syncwarp();

        // ---- aggregation: packed over j pairs; lane owns cols (l, l+32) ----
        ull acc[4][2];
        #pragma unroll
        for (int rr = 0; rr < 4; ++rr){ acc[rr][0] = 0; acc[rr][1] = 0; }
        #pragma unroll 4
        for (int j0 = 0; j0 < 256; j0 += 4){
            ulonglong2 hA = *(const ulonglong2*)(hA_base + j0);
            ulonglong2 hB = *(const ulonglong2*)(hB_base + j0);
            #pragma unroll
            for (int rr = 0; rr < 4; ++rr){
                ulonglong2 pp = *(const ulonglong2*)(pw + rr*Nc + j0);
                ffma2(acc[rr][0], pp.x, hA.x);
                ffma2(acc[rr][0], pp.y, hA.y);
                ffma2(acc[rr][1], pp.x, hB.x);
                ffma2(acc[rr][1], pp.y, hB.y);
            }
        }
        __syncwarp();

        // ---- LayerNorm + ELU ----
        #pragma unroll
        for (int rr = 0; rr < 4; ++rr){
            float2 u0 = unpack2(acc[rr][0]);
            float2 u1 = unpack2(acc[rr][1]);
            float a0 = u0.x + u0.y, a1 = u1.x + u1.y;
            float s1 = warp_sum(a0 + a1);
            float s2 = warp_sum(a0*a0 + a1*a1);
            float mean = s1 * (1.f/64.f);
            float var  = s2 * (1.f/64.f) - mean*mean;
            float rstd = rsqrtf(var + 1e-5f);
            float e0 = (a0-mean)*rstd*gm0 + bt0;
            float e1 = (a1-mean)*rstd*gm1 + bt1;
            e0 = e0 > 0.f ? e0 : (__expf(e0) - 1.f);
            e1 = e1 > 0.f ? e1 : (__expf(e1) - 1.f);
            int i = half*128 + w*16 + g*4 + rr;
            d_g[((size_t)m*Nc + i)*Hc + lane]      = e0;
            d_g[((size_t)m*Nc + i)*Hc + lane + 32] = e1;
        }
    }
}

// ------- residual + gated combine + transpose (4 rows / block) -----------
__global__ void __launch_bounds__(256) k_comb(const float* __restrict__ X,
    const float* __restrict__ Wr, const float* __restrict__ br,
    const float* __restrict__ alpha)
{
    const int t = threadIdx.x;
    const int row = blockIdx.x*4 + (t>>6);
    const int h = t & 63;
    __shared__ float xr[4][Fc+1];
    if (t < 128){
        int rr = t>>5, f = t&31;
        xr[rr][f] = X[(size_t)(blockIdx.x*4 + rr)*Fc + f];
    }
    __syncthreads();
    const int rr = t>>6;
    float acc = br[h];
    #pragma unroll
    for (int f = 0; f < Fc; ++f) acc += xr[rr][f] * Wr[f*Hc + h];
    float gate = fminf(fmaxf(alpha[0], 0.f), 1.f);
    int m = row >> 8, n = row & 255;
    int b = m >> 6, s = m & 63;
    d_seq[(((size_t)b*Nc + n)*Tc + s)*Hc + h] = acc + gate * d_g[(size_t)row*Hc + h];
}

// ---------- LSTM input gates: both dirs share row tile; wt prefetch ------
#define XPAD 36
template<int IN_, bool L1>
__global__ void __launch_bounds__(256) k_xg(const float* __restrict__ Wih,
    const float* __restrict__ bih, const float* __restrict__ bhh)
{
    const int r    = blockIdx.x >> 1;
    const int half = blockIdx.x & 1;
    const int k    = threadIdx.x;
    __shared__ __align__(16) float rowsT[IN_*XPAD];   // [hh][q]

    #pragma unroll
    for (int i = 0; i < IN_/8; ++i){
        int idx = k + 256*i;
        int hh = idx & (IN_-1);
        int q  = idx >> (IN_==64?6:7);
        int it = half*32 + q;
        float v;
        if (!L1){
            v = d_seq[((size_t)r*Tc + it)*Hc + hh];
        } else {
            if (hh < 64) v = d_hs0[((size_t)r*Tc + it)*Hc + hh];
            else         v = d_hs0[(((size_t)Rc + r)*Tc + (Tc-1-it))*Hc + (hh-64)];
        }
        rowsT[hh*XPAD + q] = v;
    }
    __syncthreads();

    const float* WA = Wih;
    const float* WB = Wih + IN_*G4c;
    float bvA = bih[k] + bhh[k];
    float bvB = bih[G4c + k] + bhh[G4c + k];
    ull accA[16], accB[16];
    #pragma unroll
    for (int i = 0; i < 16; ++i){ accA[i] = pack2(bvA,bvA); accB[i] = pack2(bvB,bvB); }

    // software-pipelined weight loads: fetch hh+1 while computing hh
    float wa = WA[k], wb = WB[k];
    #pragma unroll 2
    for (int hh = 0; hh < IN_; ++hh){
        int hn = (hh+1 < IN_) ? hh+1 : hh;
        float wan = WA[hn*G4c + k];
        float wbn = WB[hn*G4c + k];
        ull wda = pack2(wa,wa), wdb = pack2(wb,wb);
        const ulonglong2* rp = (const ulonglong2*)&rowsT[hh*XPAD];
        #pragma unroll
        for (int p = 0; p < 4; ++p){
            ulonglong2 rv = rp[p];
            ffma2(accA[4*p],   rv.x, wda);
            ffma2(accA[4*p+1], rv.y, wda);
            ffma2(accB[4*p],   rv.x, wdb);
            ffma2(accB[4*p+1], rv.y, wdb);
        }
        const ulonglong2* rp2 = rp + 4;
        #pragma unroll
        for (int p = 0; p < 4; ++p){
            ulonglong2 rv = rp2[p];
            ffma2(accA[4*p+2], rv.x, wda);
            ffma2(accA[4*p+3], rv.y, wda);
            ffma2(accB[4*p+2], rv.x, wdb);
            ffma2(accB[4*p+3], rv.y, wdb);
        }
        wa = wan; wb = wbn;
    }

    // accA[4p]:q(4p,4p+1)  accA[4p+1]:q(4p+2,4p+3)
    // accA[4p+2]:q(16+4p,+1)  accA[4p+3]:q(16+4p+2,+3)
    #pragma unroll
    for (int p = 0; p < 4; ++p){
        #pragma unroll
        for (int u = 0; u < 4; ++u){
            int q = (u < 2) ? (4*p + 2*u) : (16 + 4*p + 2*(u-2));
            float2 fa = unpack2(accA[4*p+u]);
            float2 fb = unpack2(accB[4*p+u]);
            int it0 = half*32 + q;
            size_t b0 = ((size_t)r*Tc + it0)*G4c + k;
            d_xg[b0]       = fa.x;
            d_xg[b0 + G4c] = fa.y;
            size_t b1 = (((size_t)Rc + r)*Tc + (Tc-1-it0))*G4c + k;
            d_xg[b1]       = fb.x;
            d_xg[b1 - G4c] = fb.y;
        }
    }
}

// --------- LSTM recurrence (f32x2, 8 seqs/block, xg prefetch) ------------
template<bool L1>
__global__ void __launch_bounds__(256) k_rec(const float* __restrict__ Whh)
{
    int dir = blockIdx.y;
    int r0  = blockIdx.x * 8;
    int k   = threadIdx.x;
    __shared__ __align__(16) float hsm[8][Hc];
    __shared__ float gsm[8][G4c];

    ull w2[32];
    const float* Wd = Whh + dir*Hc*G4c;
    #pragma unroll
    for (int i = 0; i < 32; ++i)
        w2[i] = pack2(Wd[(2*i)*G4c + k], Wd[(2*i+1)*G4c + k]);

    const int hid = k & 63, rA = k >> 6, rB = 4 + (k >> 6);
    hsm[rA][hid] = 0.f;
    hsm[rB][hid] = 0.f;
    float cc0 = 0.f, cc1 = 0.f;

    const float* xgd = d_xg + ((size_t)dir*Rc + r0)*Tc*G4c;
    // prefetch tau=0 gate inputs before first barrier
    float xv[8];
    #pragma unroll
    for (int rr = 0; rr < 8; ++rr)
        xv[rr] = xgd[((size_t)rr*Tc)*G4c + k];
    __syncthreads();

    for (int tau = 0; tau < Tc; ++tau){
        // matvec first (no xv dependency); xv added at the gsm write
        #pragma unroll
        for (int rr = 0; rr < 8; ++rr){
            ull a0 = 0, a1 = 0;
            const ulonglong2* hp = (const ulonglong2*)hsm[rr];
            #pragma unroll
            for (int i = 0; i < 16; ++i){
                ulonglong2 hv = hp[i];
                ffma2(a0, hv.x, w2[2*i]);
                ffma2(a1, hv.y, w2[2*i+1]);
            }
            float2 f0 = unpack2(a0), f1 = unpack2(a1);
            gsm[rr][k] = (f0.x + f1.x) + (f0.y + f1.y) + xv[rr];
        }
        // issue tau+1 loads before the barrier: overlap with sync + gates
        const int tn = (tau+1 < Tc) ? tau+1 : tau;
        float xn[8];
        #pragma unroll
        for (int rr = 0; rr < 8; ++rr)
            xn[rr] = xgd[((size_t)rr*Tc + tn)*G4c + k];
        __syncthreads();
        {
            float gi = gsm[rA][hid],     gf = gsm[rA][64+hid];
            float gg = gsm[rA][128+hid], go = gsm[rA][192+hid];
            float cn = sigfast(gf)*cc0 + sigfast(gi)*tanhfast(gg);
            float hn = sigfast(go)*tanhfast(cn);
            cc0 = cn; hsm[rA][hid] = hn;
            if (!L1) d_hs0[((size_t)(dir*Rc + r0 + rA)*Tc + tau)*Hc + hid] = hn;
        }
        {
            float gi = gsm[rB][hid],     gf = gsm[rB][64+hid];
            float gg = gsm[rB][128+hid], go = gsm[rB][192+hid];
            float cn = sigfast(gf)*cc1 + sigfast(gi)*tanhfast(gg);
            float hn = sigfast(go)*tanhfast(cn);
            cc1 = cn; hsm[rB][hid] = hn;
            if (!L1) d_hs0[((size_t)(dir*Rc + r0 + rB)*Tc + tau)*Hc + hid] = hn;
        }
        #pragma unroll
        for (int rr = 0; rr < 8; ++rr) xv[rr] = xn[rr];
        __syncthreads();
    }
    if (L1){
        d_hlast[(size_t)(dir*Rc + r0 + rA)*Hc + hid] = hsm[rA][hid];
        d_hlast[(size_t)(dir*Rc + r0 + rB)*Hc + hid] = hsm[rB][hid];
    }
}

// --------------------------- final FC ------------------------------------
__global__ void __launch_bounds__(128) k_fc(const float* __restrict__ fcW,
    const float* __restrict__ fcb, float* __restrict__ out)
{
    int r = blockIdx.x * blockDim.x + threadIdx.x;
    if (r >= Rc) return;
    float acc = fcb[0];
    #pragma unroll
    for (int hh = 0; hh < Hc; ++hh) acc += d_hlast[(size_t)r*Hc + hh]        * fcW[hh];
    #pragma unroll
    for (int hh = 0; hh < Hc; ++hh) acc += d_hlast[((size_t)Rc + r)*Hc + hh] * fcW[64 + hh];
    out[r] = acc;
}

// --------------------------------------------------------------------------
extern "C" void kernel_launch(void* const* d_in, const int* in_sizes, int n_in,
                              void* d_out, int out_size)
{
    const float* x       = (const float*)d_in[0];
    const float* adj     = (const float*)d_in[1];
    const float* gat0_W  = (const float*)d_in[2];
    const float* gat0_a  = (const float*)d_in[3];
    const float* gat0_g  = (const float*)d_in[4];
    const float* gat0_b  = (const float*)d_in[5];
    const float* gat1_W  = (const float*)d_in[6];
    const float* gat1_a  = (const float*)d_in[7];
    const float* gat1_g  = (const float*)d_in[8];
    const float* gat1_b  = (const float*)d_in[9];
    const float* res_W   = (const float*)d_in[10];
    const float* res_b   = (const float*)d_in[11];
    const float* alpha   = (const float*)d_in[12];
    const float* l0_Wih  = (const float*)d_in[13];
    const float* l0_Whh  = (const float*)d_in[14];
    const float* l0_bih  = (const float*)d_in[15];
    const float* l0_bhh  = (const float*)d_in[16];
    const float* l1_Wih  = (const float*)d_in[17];
    const float* l1_Whh  = (const float*)d_in[18];
    const float* l1_bih  = (const float*)d_in[19];
    const float* l1_bhh  = (const float*)d_in[20];
    const float* fc_W    = (const float*)d_in[21];
    const float* fc_b    = (const float*)d_in[22];
    float* out = (float*)d_out;

    cudaFuncSetAttribute(k_attn, cudaFuncAttributeMaxDynamicSharedMemorySize, ATTN_SMEM);

    // GAT layer 0
    k_proj<Fc, false><<<Mc*Nc/4, 256>>>(x, gat0_W, gat0_a);
    k_attn<<<dim3(Mc, 2), 256, ATTN_SMEM>>>(adj, gat0_g, gat0_b);
    // GAT layer 1
    k_proj<Hc, true><<<Mc*Nc/4, 256>>>(nullptr, gat1_W, gat1_a);
    k_attn<<<dim3(Mc, 2), 256, ATTN_SMEM>>>(adj, gat1_g, gat1_b);
    // residual combine + transpose to sequences
    k_comb<<<Mc*Nc/4, 256>>>(x, res_W, res_b, alpha);
    // BiLSTM layer 0
    k_xg<Hc,   false><<<Rc*2, 256>>>(l0_Wih, l0_bih, l0_bhh);
    k_rec<false><<<dim3(Rc/8, 2), 256>>>(l0_Whh);
    // BiLSTM layer 1
    k_xg<2*Hc, true><<<Rc*2, 256>>>(l1_Wih, l1_bih, l1_bhh);
    k_rec<true><<<dim3(Rc/8, 2), 256>>>(l1_Whh);
    // final FC
    k_fc<<<(Rc + 127)/128, 128>>>(fc_W, fc_b, out);
}

// round 15
// speedup vs baseline: 2.0190x; 1.0548x over previous
#include <cuda_runtime.h>
#include <cuda_bf16.h>
#include <stdint.h>
#include <math.h>

typedef unsigned long long ull;

#define Bc 4
#define Sc 64
#define Nc 256
#define Fc 32
#define Hc 64
#define Mc (Bc*Sc)     // 256 graphs
#define Rc (Bc*Nc)     // 1024 sequences
#define Tc Sc          // 64 timesteps
#define G4c (4*Hc)     // 256 gate columns
#define NEGV (-9e15f)

// ---------------- device scratch ----------------
__device__ float d_h[Mc*Nc*Hc];          // row-major [m][n][h]
__device__ float d_g[Mc*Nc*Hc];          // row-major [m][n][h]
__device__ float d_si[Mc*Nc];
__device__ float d_sj[Mc*Nc];
__device__ float d_seq[Rc*Tc*Hc];
__device__ float d_xg[2*Rc*Tc*G4c];
__device__ float d_hs0[2*Rc*Tc*Hc];
__device__ float d_hlast[2*Rc*Hc];

__device__ __forceinline__ float warp_sum(float v){
    #pragma unroll
    for (int o=16;o;o>>=1) v += __shfl_xor_sync(0xffffffffu, v, o);
    return v;
}
__device__ __forceinline__ float warp_max(float v){
    #pragma unroll
    for (int o=16;o;o>>=1) v = fmaxf(v, __shfl_xor_sync(0xffffffffu, v, o));
    return v;
}
__device__ __forceinline__ void ffma2(ull& acc, ull a, ull b){
    asm("fma.rn.f32x2 %0, %1, %2, %0;" : "+l"(acc) : "l"(a), "l"(b));
}
__device__ __forceinline__ ull pack2(float x, float y){
    ull r; asm("mov.b64 %0, {%1, %2};" : "=l"(r) : "f"(x), "f"(y)); return r;
}
__device__ __forceinline__ float2 unpack2(ull v){
    float2 f; asm("mov.b64 {%0, %1}, %2;" : "=f"(f.x), "=f"(f.y) : "l"(v)); return f;
}
__device__ __forceinline__ float tanhfast(float x){
    float y; asm("tanh.approx.f32 %0, %1;" : "=f"(y) : "f"(x)); return y;
}
__device__ __forceinline__ float sigfast(float x){
    return fmaf(0.5f, tanhfast(0.5f*x), 0.5f);
}
// warp-level bf16 MMA (baseline PTX, sm_80+ -- works on compute_103)
__device__ __forceinline__ void hmma(float& c0, float& c1, float& c2, float& c3,
    uint32_t a0, uint32_t a1, uint32_t a2, uint32_t a3, uint32_t b0, uint32_t b1)
{
    asm volatile(
        "mma.sync.aligned.m16n8k16.row.col.f32.bf16.bf16.f32 "
        "{%0,%1,%2,%3}, {%4,%5,%6,%7}, {%8,%9}, {%0,%1,%2,%3};"
        : "+f"(c0), "+f"(c1), "+f"(c2), "+f"(c3)
        : "r"(a0), "r"(a1), "r"(a2), "r"(a3), "r"(b0), "r"(b1));
}

// ---------------- GAT projection: 4 rows per block ----------------
template<int FIN_, bool FROM_G>
__global__ void __launch_bounds__(256) k_proj(const float* __restrict__ X,
    const float* __restrict__ W, const float* __restrict__ a)
{
    const int t = threadIdx.x;
    const int grp = t >> 6, h = t & 63;
    const int row0 = blockIdx.x * 4;
    __shared__ float xr[4][FIN_];
    __shared__ float red2[2][4][2];
    const float* src = FROM_G ? d_g : X;
    #pragma unroll
    for (int i = 0; i < (4*FIN_+255)/256; ++i){
        int idx = t + 256*i;
        if (idx < 4*FIN_){
            int rr = idx / FIN_, f = idx % FIN_;
            xr[rr][f] = src[(size_t)(row0+rr)*FIN_ + f];
        }
    }
    __syncthreads();
    float acc = 0.f;
    #pragma unroll
    for (int f = 0; f < FIN_; ++f) acc += xr[grp][f] * W[f*Hc + h];
    d_h[(size_t)(row0+grp)*Hc + h] = acc;
    float v1 = warp_sum(acc * a[h]);
    float v2 = warp_sum(acc * a[Hc + h]);
    const int wig = (t >> 5) & 1;
    if ((t & 31) == 0){ red2[0][grp][wig] = v1; red2[1][grp][wig] = v2; }
    __syncthreads();
    if (h == 0){
        d_si[row0+grp] = red2[0][grp][0] + red2[0][grp][1];
        d_sj[row0+grp] = red2[1][grp][0] + red2[1][grp][1];
    }
}

// --------- GAT attention: rr=4 rows/warp (proven), f32x2 --------------
#define HST 268
#define ATTN_SMEM ((Hc*HST + 8*4*Nc + 2*Nc) * 4)
__global__ void __launch_bounds__(256) k_attn(const float* __restrict__ adj,
    const float* __restrict__ gamma, const float* __restrict__ beta)
{
    extern __shared__ float sm[];
    float* h_smT = sm;
    float* p_sm  = sm + Hc*HST;
    float* si_sm = p_sm + 8*4*Nc;
    float* sj_sm = si_sm + Nc;

    const int m = blockIdx.x;
    const int half = blockIdx.y;
    const int t = threadIdx.x, w = t>>5, lane = t&31;

    const float4* hg4 = (const float4*)(d_h + (size_t)m*Nc*Hc);
    #pragma unroll
    for (int i = 0; i < 16; ++i){
        int f4 = t + 256*i;
        int n  = f4 >> 4;
        int hq = f4 & 15;
        float4 v = hg4[f4];
        #pragma unroll
        for (int u = 0; u < 4; ++u){
            int c = (u + hq) & 3;
            float a0 = (c & 1) ? v.y : v.x;
            float a1 = (c & 1) ? v.w : v.z;
            float val = (c & 2) ? a1 : a0;
            h_smT[(4*hq + c)*HST + n] = val;
        }
    }
    si_sm[t] = d_si[m*Nc + t];
    sj_sm[t] = d_sj[m*Nc + t];
    __syncthreads();

    const float gm0 = gamma[lane], gm1 = gamma[lane+32];
    const float bt0 = beta[lane],  bt1 = beta[lane+32];
    float* pw = p_sm + w*(4*Nc);
    const float* hA_base = h_smT + lane*HST;
    const float* hB_base = h_smT + (lane+32)*HST;

    for (int g = 0; g < 4; ++g){
        #pragma unroll
        for (int rr = 0; rr < 4; ++rr){
            int i = half*128 + w*16 + g*4 + rr;
            float si = si_sm[i];
            const float* arow = adj + ((size_t)m*Nc + i)*Nc;
            float ev[8]; float mx = -3.402823466e38f;
            #pragma unroll
            for (int q = 0; q < 8; ++q){
                int j = q*32 + lane;
                float e = si + sj_sm[j];
                e = e > 0.f ? e : 0.2f*e;
                if (arow[j] <= 0.f) e = NEGV;
                ev[q] = e; mx = fmaxf(mx, e);
            }
            mx = warp_max(mx);
            float s = 0.f;
            #pragma unroll
            for (int q = 0; q < 8; ++q){ ev[q] = __expf(ev[q]-mx); s += ev[q]; }
            s = warp_sum(s);
            float inv = 1.f / s;
            #pragma unroll
            for (int q = 0; q < 8; ++q) pw[rr*Nc + q*32 + lane] = ev[q]*inv;
        }
        __syncwarp();

        ull acc[4][2];
        #pragma unroll
        for (int rr = 0; rr < 4; ++rr){ acc[rr][0] = 0; acc[rr][1] = 0; }
        #pragma unroll 4
        for (int j0 = 0; j0 < 256; j0 += 4){
            ulonglong2 hA = *(const ulonglong2*)(hA_base + j0);
            ulonglong2 hB = *(const ulonglong2*)(hB_base + j0);
            #pragma unroll
            for (int rr = 0; rr < 4; ++rr){
                ulonglong2 pp = *(const ulonglong2*)(pw + rr*Nc + j0);
                ffma2(acc[rr][0], pp.x, hA.x);
                ffma2(acc[rr][0], pp.y, hA.y);
                ffma2(acc[rr][1], pp.x, hB.x);
                ffma2(acc[rr][1], pp.y, hB.y);
            }
        }
        __syncwarp();

        #pragma unroll
        for (int rr = 0; rr < 4; ++rr){
            float2 u0 = unpack2(acc[rr][0]);
            float2 u1 = unpack2(acc[rr][1]);
            float a0 = u0.x + u0.y, a1 = u1.x + u1.y;
            float s1 = warp_sum(a0 + a1);
            float s2 = warp_sum(a0*a0 + a1*a1);
            float mean = s1 * (1.f/64.f);
            float var  = s2 * (1.f/64.f) - mean*mean;
            float rstd = rsqrtf(var + 1e-5f);
            float e0 = (a0-mean)*rstd*gm0 + bt0;
            float e1 = (a1-mean)*rstd*gm1 + bt1;
            e0 = e0 > 0.f ? e0 : (__expf(e0) - 1.f);
            e1 = e1 > 0.f ? e1 : (__expf(e1) - 1.f);
            int i = half*128 + w*16 + g*4 + rr;
            d_g[((size_t)m*Nc + i)*Hc + lane]      = e0;
            d_g[((size_t)m*Nc + i)*Hc + lane + 32] = e1;
        }
    }
}

// ------- residual + gated combine + transpose (4 rows / block) -----------
__global__ void __launch_bounds__(256) k_comb(const float* __restrict__ X,
    const float* __restrict__ Wr, const float* __restrict__ br,
    const float* __restrict__ alpha)
{
    const int t = threadIdx.x;
    const int row = blockIdx.x*4 + (t>>6);
    const int h = t & 63;
    __shared__ float xr[4][Fc+1];
    if (t < 128){
        int rr = t>>5, f = t&31;
        xr[rr][f] = X[(size_t)(blockIdx.x*4 + rr)*Fc + f];
    }
    __syncthreads();
    const int rr = t>>6;
    float acc = br[h];
    #pragma unroll
    for (int f = 0; f < Fc; ++f) acc += xr[rr][f] * Wr[f*Hc + h];
    float gate = fminf(fmaxf(alpha[0], 0.f), 1.f);
    int m = row >> 8, n = row & 255;
    int b = m >> 6, s = m & 63;
    d_seq[(((size_t)b*Nc + n)*Tc + s)*Hc + h] = acc + gate * d_g[(size_t)row*Hc + h];
}

// ========== LSTM input gates via warp-MMA (bf16 hi/lo, 3 passes) =========
// Block = (2 sequences, 1 dir), 256 threads / 8 warps.
// D[128, 256] = A[128, IN] x W[IN, 256]; warp w owns m-tile rows [16w,16w+16),
// loops 32 n-tiles of 8 cols. A/B in smem row-padded to IN+8 bf16 (conflict-free).
template<int IN_, bool L1>
__global__ void __launch_bounds__(256) k_xg_hmma(const float* __restrict__ Wih,
    const float* __restrict__ bih, const float* __restrict__ bhh)
{
    constexpr int KT = IN_/16;            // k-tiles
    constexpr int SA = IN_ + 8;           // padded row stride (bf16 units)
    constexpr int A_BYTES = 128*SA*2;
    constexpr int B_BYTES = 256*SA*2;
    constexpr int AHo = 0;
    constexpr int ALo = A_BYTES;
    constexpr int BHo = 2*A_BYTES;
    constexpr int BLo = 2*A_BYTES + B_BYTES;
    constexpr int BIAS = 2*A_BYTES + 2*B_BYTES;

    extern __shared__ char xsm[];
    const int tid = threadIdx.x, wid = tid>>5, lane = tid&31;
    const int r0 = blockIdx.x*2, dir = blockIdx.y;

    // ---- A tile: inputs -> bf16 hi/lo [row][k] ----
    for (int idx = tid; idx < 128*IN_; idx += 256){
        int row = idx / IN_, k = idx % IN_;
        int si = row>>6, t = row&63;
        float v;
        if (!L1){
            v = d_seq[((size_t)(r0+si)*Tc + t)*Hc + k];
        } else {
            v = (k < 64) ? d_hs0[((size_t)(r0+si)*Tc + t)*Hc + k]
                         : d_hs0[(((size_t)Rc + (r0+si))*Tc + (63-t))*Hc + (k-64)];
        }
        __nv_bfloat16 hi = __float2bfloat16(v);
        __nv_bfloat16 lo = __float2bfloat16(v - __bfloat162float(hi));
        int off = (row*SA + k)*2;
        *(__nv_bfloat16*)(xsm + AHo + off) = hi;
        *(__nv_bfloat16*)(xsm + ALo + off) = lo;
    }
    // ---- B tile: Bs[n][k] = W[k][n], bf16 hi/lo ----
    const float* Wd = Wih + (size_t)dir*IN_*G4c;
    for (int idx = tid; idx < IN_*256; idx += 256){
        int k = idx >> 8, n = idx & 255;
        float v = Wd[(size_t)k*G4c + n];
        __nv_bfloat16 hi = __float2bfloat16(v);
        __nv_bfloat16 lo = __float2bfloat16(v - __bfloat162float(hi));
        int off = (n*SA + k)*2;
        *(__nv_bfloat16*)(xsm + BHo + off) = hi;
        *(__nv_bfloat16*)(xsm + BLo + off) = lo;
    }
    ((float*)(xsm + BIAS))[tid] = bih[dir*G4c + tid] + bhh[dir*G4c + tid];
    __syncthreads();

    // ---- per-warp MMA: m-tile = wid ----
    const int r_q = lane >> 2, c_q = lane & 3;         // quad decomposition
    const int arow = 16*wid + r_q;
    // A fragments (register-resident): a0:(r, 2c+16kt) a1:(r+8) a2:(k+8) a3:(both)
    uint32_t aH[KT][4], aL[KT][4];
    #pragma unroll
    for (int kt = 0; kt < KT; ++kt){
        int kc = c_q*2 + kt*16;
        int o00 = (arow*SA + kc)*2,      o10 = ((arow+8)*SA + kc)*2;
        int o01 = (arow*SA + kc + 8)*2,  o11 = ((arow+8)*SA + kc + 8)*2;
        aH[kt][0] = *(const uint32_t*)(xsm + AHo + o00);
        aH[kt][1] = *(const uint32_t*)(xsm + AHo + o10);
        aH[kt][2] = *(const uint32_t*)(xsm + AHo + o01);
        aH[kt][3] = *(const uint32_t*)(xsm + AHo + o11);
        aL[kt][0] = *(const uint32_t*)(xsm + ALo + o00);
        aL[kt][1] = *(const uint32_t*)(xsm + ALo + o10);
        aL[kt][2] = *(const uint32_t*)(xsm + ALo + o01);
        aL[kt][3] = *(const uint32_t*)(xsm + ALo + o11);
    }

    const int si = arow >> 6, t8 = (arow+8) & 63, t0 = arow & 63;
    const int tau0 = dir ? (63 - t0) : t0;
    const int tau8 = dir ? (63 - t8) : t8;
    const int si8 = (arow+8) >> 6;
    float* ob0 = d_xg + ((size_t)(dir*Rc + r0 + si )*Tc + tau0)*G4c;
    float* ob8 = d_xg + ((size_t)(dir*Rc + r0 + si8)*Tc + tau8)*G4c;
    const float* bsm = (const float*)(xsm + BIAS);

    for (int nt = 0; nt < 32; ++nt){
        const int bn = nt*8 + r_q;                      // B fragment column
        float c0 = 0.f, c1 = 0.f, c2 = 0.f, c3 = 0.f;
        #pragma unroll
        for (int kt = 0; kt < KT; ++kt){
            int kc = c_q*2 + kt*16;
            uint32_t bh0 = *(const uint32_t*)(xsm + BHo + (bn*SA + kc)*2);
            uint32_t bh1 = *(const uint32_t*)(xsm + BHo + (bn*SA + kc + 8)*2);
            uint32_t bl0 = *(const uint32_t*)(xsm + BLo + (bn*SA + kc)*2);
            uint32_t bl1 = *(const uint32_t*)(xsm + BLo + (bn*SA + kc + 8)*2);
            hmma(c0,c1,c2,c3, aH[kt][0],aH[kt][1],aH[kt][2],aH[kt][3], bh0,bh1);
            hmma(c0,c1,c2,c3, aL[kt][0],aL[kt][1],aL[kt][2],aL[kt][3], bh0,bh1);
            hmma(c0,c1,c2,c3, aH[kt][0],aH[kt][1],aH[kt][2],aH[kt][3], bl0,bl1);
        }
        const int col = nt*8 + c_q*2;
        float2 o0 = make_float2(c0 + bsm[col], c1 + bsm[col+1]);
        float2 o1 = make_float2(c2 + bsm[col], c3 + bsm[col+1]);
        *(float2*)(ob0 + col) = o0;
        *(float2*)(ob8 + col) = o1;
    }
}

// --------- LSTM recurrence (f32x2, 8 seqs/block, xg prefetch) ------------
template<bool L1>
__global__ void __launch_bounds__(256) k_rec(const float* __restrict__ Whh)
{
    int dir = blockIdx.y;
    int r0  = blockIdx.x * 8;
    int k   = threadIdx.x;
    __shared__ __align__(16) float hsm[8][Hc];
    __shared__ float gsm[8][G4c];

    ull w2[32];
    const float* Wd = Whh + dir*Hc*G4c;
    #pragma unroll
    for (int i = 0; i < 32; ++i)
        w2[i] = pack2(Wd[(2*i)*G4c + k], Wd[(2*i+1)*G4c + k]);

    const int hid = k & 63, rA = k >> 6, rB = 4 + (k >> 6);
    hsm[rA][hid] = 0.f;
    hsm[rB][hid] = 0.f;
    float cc0 = 0.f, cc1 = 0.f;

    const float* xgd = d_xg + ((size_t)dir*Rc + r0)*Tc*G4c;
    float xv[8];
    #pragma unroll
    for (int rr = 0; rr < 8; ++rr)
        xv[rr] = xgd[((size_t)rr*Tc)*G4c + k];
    __syncthreads();

    for (int tau = 0; tau < Tc; ++tau){
        #pragma unroll
        for (int rr = 0; rr < 8; ++rr){
            ull a0 = 0, a1 = 0;
            const ulonglong2* hp = (const ulonglong2*)hsm[rr];
            #pragma unroll
            for (int i = 0; i < 16; ++i){
                ulonglong2 hv = hp[i];
                ffma2(a0, hv.x, w2[2*i]);
                ffma2(a1, hv.y, w2[2*i+1]);
            }
            float2 f0 = unpack2(a0), f1 = unpack2(a1);
            gsm[rr][k] = (f0.x + f1.x) + (f0.y + f1.y) + xv[rr];
        }
        const int tn = (tau+1 < Tc) ? tau+1 : tau;
        float xn[8];
        #pragma unroll
        for (int rr = 0; rr < 8; ++rr)
            xn[rr] = xgd[((size_t)rr*Tc + tn)*G4c + k];
        __syncthreads();
        {
            float gi = gsm[rA][hid],     gf = gsm[rA][64+hid];
            float gg = gsm[rA][128+hid], go = gsm[rA][192+hid];
            float cn = sigfast(gf)*cc0 + sigfast(gi)*tanhfast(gg);
            float hn = sigfast(go)*tanhfast(cn);
            cc0 = cn; hsm[rA][hid] = hn;
            if (!L1) d_hs0[((size_t)(dir*Rc + r0 + rA)*Tc + tau)*Hc + hid] = hn;
        }
        {
            float gi = gsm[rB][hid],     gf = gsm[rB][64+hid];
            float gg = gsm[rB][128+hid], go = gsm[rB][192+hid];
            float cn = sigfast(gf)*cc1 + sigfast(gi)*tanhfast(gg);
            float hn = sigfast(go)*tanhfast(cn);
            cc1 = cn; hsm[rB][hid] = hn;
            if (!L1) d_hs0[((size_t)(dir*Rc + r0 + rB)*Tc + tau)*Hc + hid] = hn;
        }
        #pragma unroll
        for (int rr = 0; rr < 8; ++rr) xv[rr] = xn[rr];
        __syncthreads();
    }
    if (L1){
        d_hlast[(size_t)(dir*Rc + r0 + rA)*Hc + hid] = hsm[rA][hid];
        d_hlast[(size_t)(dir*Rc + r0 + rB)*Hc + hid] = hsm[rB][hid];
    }
}

// --------------------------- final FC ------------------------------------
__global__ void __launch_bounds__(128) k_fc(const float* __restrict__ fcW,
    const float* __restrict__ fcb, float* __restrict__ out)
{
    int r = blockIdx.x * blockDim.x + threadIdx.x;
    if (r >= Rc) return;
    float acc = fcb[0];
    #pragma unroll
    for (int hh = 0; hh < Hc; ++hh) acc += d_hlast[(size_t)r*Hc + hh]        * fcW[hh];
    #pragma unroll
    for (int hh = 0; hh < Hc; ++hh) acc += d_hlast[((size_t)Rc + r)*Hc + hh] * fcW[64 + hh];
    out[r] = acc;
}

// --------------------------------------------------------------------------
extern "C" void kernel_launch(void* const* d_in, const int* in_sizes, int n_in,
                              void* d_out, int out_size)
{
    const float* x       = (const float*)d_in[0];
    const float* adj     = (const float*)d_in[1];
    const float* gat0_W  = (const float*)d_in[2];
    const float* gat0_a  = (const float*)d_in[3];
    const float* gat0_g  = (const float*)d_in[4];
    const float* gat0_b  = (const float*)d_in[5];
    const float* gat1_W  = (const float*)d_in[6];
    const float* gat1_a  = (const float*)d_in[7];
    const float* gat1_g  = (const float*)d_in[8];
    const float* gat1_b  = (const float*)d_in[9];
    const float* res_W   = (const float*)d_in[10];
    const float* res_b   = (const float*)d_in[11];
    const float* alpha   = (const float*)d_in[12];
    const float* l0_Wih  = (const float*)d_in[13];
    const float* l0_Whh  = (const float*)d_in[14];
    const float* l0_bih  = (const float*)d_in[15];
    const float* l0_bhh  = (const float*)d_in[16];
    const float* l1_Wih  = (const float*)d_in[17];
    const float* l1_Whh  = (const float*)d_in[18];
    const float* l1_bih  = (const float*)d_in[19];
    const float* l1_bhh  = (const float*)d_in[20];
    const float* fc_W    = (const float*)d_in[21];
    const float* fc_b    = (const float*)d_in[22];
    float* out = (float*)d_out;

    // dynamic smem: 2*A + 2*B + bias (bf16 rows padded to IN+8)
    const int xg0_smem = 2*(128*(Hc+8)*2)    + 2*(256*(Hc+8)*2)    + 1024;   // ~112 KB
    const int xg1_smem = 2*(128*(2*Hc+8)*2)  + 2*(256*(2*Hc+8)*2)  + 1024;   // ~210 KB
    cudaFuncSetAttribute(k_attn, cudaFuncAttributeMaxDynamicSharedMemorySize, ATTN_SMEM);
    cudaFuncSetAttribute(k_xg_hmma<Hc,false>,  cudaFuncAttributeMaxDynamicSharedMemorySize, xg0_smem);
    cudaFuncSetAttribute(k_xg_hmma<2*Hc,true>, cudaFuncAttributeMaxDynamicSharedMemorySize, xg1_smem);

    // GAT layer 0
    k_proj<Fc, false><<<Mc*Nc/4, 256>>>(x, gat0_W, gat0_a);
    k_attn<<<dim3(Mc, 2), 256, ATTN_SMEM>>>(adj, gat0_g, gat0_b);
    // GAT layer 1
    k_proj<Hc, true><<<Mc*Nc/4, 256>>>(nullptr, gat1_W, gat1_a);
    k_attn<<<dim3(Mc, 2), 256, ATTN_SMEM>>>(adj, gat1_g, gat1_b);
    // residual combine + transpose to sequences
    k_comb<<<Mc*Nc/4, 256>>>(x, res_W, res_b, alpha);
    // BiLSTM layer 0
    k_xg_hmma<Hc,   false><<<dim3(Rc/2, 2), 256, xg0_smem>>>(l0_Wih, l0_bih, l0_bhh);
    k_rec<false><<<dim3(Rc/8, 2), 256>>>(l0_Whh);
    // BiLSTM layer 1
    k_xg_hmma<2*Hc, true><<<dim3(Rc/2, 2), 256, xg1_smem>>>(l1_Wih, l1_bih, l1_bhh);
    k_rec<true><<<dim3(Rc/8, 2), 256>>>(l1_Whh);
    // final FC
    k_fc<<<(Rc + 127)/128, 128>>>(fc_W, fc_b, out);
}

// round 17
// speedup vs baseline: 2.1842x; 1.0818x over previous
#include <cuda_runtime.h>
#include <cuda_bf16.h>
#include <stdint.h>
#include <math.h>

typedef unsigned long long ull;

#define Bc 4
#define Sc 64
#define Nc 256
#define Fc 32
#define Hc 64
#define Mc (Bc*Sc)     // 256 graphs
#define Rc (Bc*Nc)     // 1024 sequences
#define Tc Sc          // 64 timesteps
#define G4c (4*Hc)     // 256 gate columns
#define NEGV (-9e15f)

// ---------------- device scratch ----------------
__device__ float d_h[Mc*Nc*Hc];          // row-major [m][n][h]
__device__ float d_g[Mc*Nc*Hc];          // row-major [m][n][h]
__device__ float d_si[Mc*Nc];
__device__ float d_sj[Mc*Nc];
__device__ float d_xg[2*Rc*Tc*G4c];
__device__ float d_hlast[2*Rc*Hc];
// bf16 hi/lo pre-converted operands (producer-side conversion)
__device__ __nv_bfloat16 d_seqh[Rc*Tc*Hc], d_seql[Rc*Tc*Hc];
__device__ __nv_bfloat16 d_hs0h[2*Rc*Tc*Hc], d_hs0l[2*Rc*Tc*Hc];
__device__ __nv_bfloat16 d_w0h[2*256*Hc],   d_w0l[2*256*Hc];    // [dir][n][k]
__device__ __nv_bfloat16 d_w1h[2*256*2*Hc], d_w1l[2*256*2*Hc];  // [dir][n][k]

__device__ __forceinline__ float warp_sum(float v){
    #pragma unroll
    for (int o=16;o;o>>=1) v += __shfl_xor_sync(0xffffffffu, v, o);
    return v;
}
__device__ __forceinline__ float warp_max(float v){
    #pragma unroll
    for (int o=16;o;o>>=1) v = fmaxf(v, __shfl_xor_sync(0xffffffffu, v, o));
    return v;
}
__device__ __forceinline__ void ffma2(ull& acc, ull a, ull b){
    asm("fma.rn.f32x2 %0, %1, %2, %0;" : "+l"(acc) : "l"(a), "l"(b));
}
__device__ __forceinline__ ull pack2(float x, float y){
    ull r; asm("mov.b64 %0, {%1, %2};" : "=l"(r) : "f"(x), "f"(y)); return r;
}
__device__ __forceinline__ float2 unpack2(ull v){
    float2 f; asm("mov.b64 {%0, %1}, %2;" : "=f"(f.x), "=f"(f.y) : "l"(v)); return f;
}
__device__ __forceinline__ float tanhfast(float x){
    float y; asm("tanh.approx.f32 %0, %1;" : "=f"(y) : "f"(x)); return y;
}
__device__ __forceinline__ float sigfast(float x){
    return fmaf(0.5f, tanhfast(0.5f*x), 0.5f);
}
__device__ __forceinline__ void hmma(float& c0, float& c1, float& c2, float& c3,
    uint32_t a0, uint32_t a1, uint32_t a2, uint32_t a3, uint32_t b0, uint32_t b1)
{
    asm volatile(
        "mma.sync.aligned.m16n8k16.row.col.f32.bf16.bf16.f32 "
        "{%0,%1,%2,%3}, {%4,%5,%6,%7}, {%8,%9}, {%0,%1,%2,%3};"
        : "+f"(c0), "+f"(c1), "+f"(c2), "+f"(c3)
        : "r"(a0), "r"(a1), "r"(a2), "r"(a3), "r"(b0), "r"(b1));
}
__device__ __forceinline__ void bf16split(float v, __nv_bfloat16& hi, __nv_bfloat16& lo){
    hi = __float2bfloat16(v);
    lo = __float2bfloat16(v - __bfloat162float(hi));
}

// -------- weight pre-convert: fp32 [dir][k][n] -> bf16 hi/lo [dir][n][k] --
__global__ void __launch_bounds__(256) k_wconv(const float* __restrict__ w0,
    const float* __restrict__ w1)
{
    int idx = blockIdx.x*256 + threadIdx.x;
    if (idx < 2*Hc*256){
        int dir = idx / (Hc*256); int rem = idx % (Hc*256);
        int k = rem >> 8, n = rem & 255;
        __nv_bfloat16 hi, lo; bf16split(w0[idx], hi, lo);
        size_t o = (size_t)dir*256*Hc + (size_t)n*Hc + k;
        d_w0h[o] = hi; d_w0l[o] = lo;
    } else {
        int j = idx - 2*Hc*256;
        if (j < 2*2*Hc*256){
            int dir = j / (2*Hc*256); int rem = j % (2*Hc*256);
            int k = rem >> 8, n = rem & 255;
            __nv_bfloat16 hi, lo; bf16split(w1[j], hi, lo);
            size_t o = (size_t)dir*256*2*Hc + (size_t)n*2*Hc + k;
            d_w1h[o] = hi; d_w1l[o] = lo;
        }
    }
}

// ---------------- GAT projection: 4 rows per block ----------------
template<int FIN_, bool FROM_G>
__global__ void __launch_bounds__(256) k_proj(const float* __restrict__ X,
    const float* __restrict__ W, const float* __restrict__ a)
{
    const int t = threadIdx.x;
    const int grp = t >> 6, h = t & 63;
    const int row0 = blockIdx.x * 4;
    __shared__ float xr[4][FIN_];
    __shared__ float red2[2][4][2];
    const float* src = FROM_G ? d_g : X;
    #pragma unroll
    for (int i = 0; i < (4*FIN_+255)/256; ++i){
        int idx = t + 256*i;
        if (idx < 4*FIN_){
            int rr = idx / FIN_, f = idx % FIN_;
            xr[rr][f] = src[(size_t)(row0+rr)*FIN_ + f];
        }
    }
    __syncthreads();
    float acc = 0.f;
    #pragma unroll
    for (int f = 0; f < FIN_; ++f) acc += xr[grp][f] * W[f*Hc + h];
    d_h[(size_t)(row0+grp)*Hc + h] = acc;
    float v1 = warp_sum(acc * a[h]);
    float v2 = warp_sum(acc * a[Hc + h]);
    const int wig = (t >> 5) & 1;
    if ((t & 31) == 0){ red2[0][grp][wig] = v1; red2[1][grp][wig] = v2; }
    __syncthreads();
    if (h == 0){
        d_si[row0+grp] = red2[0][grp][0] + red2[0][grp][1];
        d_sj[row0+grp] = red2[1][grp][0] + red2[1][grp][1];
    }
}

// --------- GAT attention: rr=4 rows/warp (proven), f32x2 --------------
#define HST 268
#define ATTN_SMEM ((Hc*HST + 8*4*Nc + 2*Nc) * 4)
__global__ void __launch_bounds__(256) k_attn(const float* __restrict__ adj,
    const float* __restrict__ gamma, const float* __restrict__ beta)
{
    extern __shared__ float sm[];
    float* h_smT = sm;
    float* p_sm  = sm + Hc*HST;
    float* si_sm = p_sm + 8*4*Nc;
    float* sj_sm = si_sm + Nc;

    const int m = blockIdx.x;
    const int half = blockIdx.y;
    const int t = threadIdx.x, w = t>>5, lane = t&31;

    const float4* hg4 = (const float4*)(d_h + (size_t)m*Nc*Hc);
    #pragma unroll
    for (int i = 0; i < 16; ++i){
        int f4 = t + 256*i;
        int n  = f4 >> 4;
        int hq = f4 & 15;
        float4 v = hg4[f4];
        #pragma unroll
        for (int u = 0; u < 4; ++u){
            int c = (u + hq) & 3;
            float a0 = (c & 1) ? v.y : v.x;
            float a1 = (c & 1) ? v.w : v.z;
            float val = (c & 2) ? a1 : a0;
            h_smT[(4*hq + c)*HST + n] = val;
        }
    }
    si_sm[t] = d_si[m*Nc + t];
    sj_sm[t] = d_sj[m*Nc + t];
    __syncthreads();

    const float gm0 = gamma[lane], gm1 = gamma[lane+32];
    const float bt0 = beta[lane],  bt1 = beta[lane+32];
    float* pw = p_sm + w*(4*Nc);
    const float* hA_base = h_smT + lane*HST;
    const float* hB_base = h_smT + (lane+32)*HST;

    for (int g = 0; g < 4; ++g){
        #pragma unroll
        for (int rr = 0; rr < 4; ++rr){
            int i = half*128 + w*16 + g*4 + rr;
            float si = si_sm[i];
            const float* arow = adj + ((size_t)m*Nc + i)*Nc;
            float ev[8]; float mx = -3.402823466e38f;
            #pragma unroll
            for (int q = 0; q < 8; ++q){
                int j = q*32 + lane;
                float e = si + sj_sm[j];
                e = e > 0.f ? e : 0.2f*e;
                if (arow[j] <= 0.f) e = NEGV;
                ev[q] = e; mx = fmaxf(mx, e);
            }
            mx = warp_max(mx);
            float s = 0.f;
            #pragma unroll
            for (int q = 0; q < 8; ++q){ ev[q] = __expf(ev[q]-mx); s += ev[q]; }
            s = warp_sum(s);
            float inv = 1.f / s;
            #pragma unroll
            for (int q = 0; q < 8; ++q) pw[rr*Nc + q*32 + lane] = ev[q]*inv;
        }
        __syncwarp();

        ull acc[4][2];
        #pragma unroll
        for (int rr = 0; rr < 4; ++rr){ acc[rr][0] = 0; acc[rr][1] = 0; }
        #pragma unroll 4
        for (int j0 = 0; j0 < 256; j0 += 4){
            ulonglong2 hA = *(const ulonglong2*)(hA_base + j0);
            ulonglong2 hB = *(const ulonglong2*)(hB_base + j0);
            #pragma unroll
            for (int rr = 0; rr < 4; ++rr){
                ulonglong2 pp = *(const ulonglong2*)(pw + rr*Nc + j0);
                ffma2(acc[rr][0], pp.x, hA.x);
                ffma2(acc[rr][0], pp.y, hA.y);
                ffma2(acc[rr][1], pp.x, hB.x);
                ffma2(acc[rr][1], pp.y, hB.y);
            }
        }
        __syncwarp();

        #pragma unroll
        for (int rr = 0; rr < 4; ++rr){
            float2 u0 = unpack2(acc[rr][0]);
            float2 u1 = unpack2(acc[rr][1]);
            float a0 = u0.x + u0.y, a1 = u1.x + u1.y;
            float s1 = warp_sum(a0 + a1);
            float s2 = warp_sum(a0*a0 + a1*a1);
            float mean = s1 * (1.f/64.f);
            float var  = s2 * (1.f/64.f) - mean*mean;
            float rstd = rsqrtf(var + 1e-5f);
            float e0 = (a0-mean)*rstd*gm0 + bt0;
            float e1 = (a1-mean)*rstd*gm1 + bt1;
            e0 = e0 > 0.f ? e0 : (__expf(e0) - 1.f);
            e1 = e1 > 0.f ? e1 : (__expf(e1) - 1.f);
            int i = half*128 + w*16 + g*4 + rr;
            d_g[((size_t)m*Nc + i)*Hc + lane]      = e0;
            d_g[((size_t)m*Nc + i)*Hc + lane + 32] = e1;
        }
    }
}

// ------ residual + combine + transpose; emits bf16 hi/lo sequences -------
__global__ void __launch_bounds__(256) k_comb(const float* __restrict__ X,
    const float* __restrict__ Wr, const float* __restrict__ br,
    const float* __restrict__ alpha)
{
    const int t = threadIdx.x;
    const int row = blockIdx.x*4 + (t>>6);
    const int h = t & 63;
    __shared__ float xr[4][Fc+1];
    if (t < 128){
        int rr = t>>5, f = t&31;
        xr[rr][f] = X[(size_t)(blockIdx.x*4 + rr)*Fc + f];
    }
    __syncthreads();
    const int rr = t>>6;
    float acc = br[h];
    #pragma unroll
    for (int f = 0; f < Fc; ++f) acc += xr[rr][f] * Wr[f*Hc + h];
    float gate = fminf(fmaxf(alpha[0], 0.f), 1.f);
    int m = row >> 8, n = row & 255;
    int b = m >> 6, s = m & 63;
    float val = acc + gate * d_g[(size_t)row*Hc + h];
    size_t off = (((size_t)b*Nc + n)*Tc + s)*Hc + h;
    __nv_bfloat16 hi, lo; bf16split(val, hi, lo);
    d_seqh[off] = hi; d_seql[off] = lo;
}

// ========== LSTM input gates via warp-MMA (pre-converted bf16) ===========
// Block = (2 sequences, 1 dir). Fill = pure u32 copies (no conversion).
// Weight arrays referenced via device symbols (NOT host-passed pointers).
template<int IN_, bool L1>
__global__ void __launch_bounds__(256) k_xg_hmma(
    const float* __restrict__ bih, const float* __restrict__ bhh)
{
    constexpr int KT = IN_/16;            // k-tiles
    constexpr int SA = IN_ + 8;           // padded row stride (bf16 units)
    constexpr int UPR = IN_/2;            // u32 units per row
    constexpr int A_BYTES = 128*SA*2;
    constexpr int B_BYTES = 256*SA*2;
    constexpr int AHo = 0;
    constexpr int ALo = A_BYTES;
    constexpr int BHo = 2*A_BYTES;
    constexpr int BLo = 2*A_BYTES + B_BYTES;
    constexpr int BIAS = 2*A_BYTES + 2*B_BYTES;

    extern __shared__ char xsm[];
    const int tid = threadIdx.x, wid = tid>>5, lane = tid&31;
    const int r0 = blockIdx.x*2, dir = blockIdx.y;

    // device-symbol weight selection (host cannot pass __device__ arrays)
    const uint32_t* wh = (const uint32_t*)((L1 ? d_w1h : d_w0h) + (size_t)dir*256*IN_);
    const uint32_t* wl = (const uint32_t*)((L1 ? d_w1l : d_w0l) + (size_t)dir*256*IN_);

    // ---- A tile: u32 copies from pre-converted sequences ----
    for (int idx = tid; idx < 128*UPR; idx += 256){
        int row = idx / UPR, j = idx % UPR;
        int si = row>>6, t = row&63;
        uint32_t vh, vl;
        if (!L1){
            size_t soff = ((size_t)(r0+si)*Tc + t)*(Hc/2) + j;
            vh = ((const uint32_t*)d_seqh)[soff];
            vl = ((const uint32_t*)d_seql)[soff];
        } else {
            size_t soff;
            if (j < 32) soff = ((size_t)(r0+si)*Tc + t)*(Hc/2) + j;
            else        soff = (((size_t)Rc + (r0+si))*Tc + (63-t))*(Hc/2) + (j-32);
            vh = ((const uint32_t*)d_hs0h)[soff];
            vl = ((const uint32_t*)d_hs0l)[soff];
        }
        int doff = (row*SA + j*2)*2;   // bytes
        *(uint32_t*)(xsm + AHo + doff) = vh;
        *(uint32_t*)(xsm + ALo + doff) = vl;
    }
    // ---- B tile: u32 copies from pre-converted transposed weights ----
    for (int idx = tid; idx < 256*UPR; idx += 256){
        int n = idx / UPR, j = idx % UPR;
        int doff = (n*SA + j*2)*2;
        *(uint32_t*)(xsm + BHo + doff) = wh[idx];
        *(uint32_t*)(xsm + BLo + doff) = wl[idx];
    }
    ((float*)(xsm + BIAS))[tid] = bih[dir*G4c + tid] + bhh[dir*G4c + tid];
    __syncthreads();

    // ---- per-warp MMA: m-tile = wid ----
    const int r_q = lane >> 2, c_q = lane & 3;
    const int arow = 16*wid + r_q;
    uint32_t aH[KT][4], aL[KT][4];
    #pragma unroll
    for (int kt = 0; kt < KT; ++kt){
        int kc = c_q*2 + kt*16;
        int o00 = (arow*SA + kc)*2,      o10 = ((arow+8)*SA + kc)*2;
        int o01 = (arow*SA + kc + 8)*2,  o11 = ((arow+8)*SA + kc + 8)*2;
        aH[kt][0] = *(const uint32_t*)(xsm + AHo + o00);
        aH[kt][1] = *(const uint32_t*)(xsm + AHo + o10);
        aH[kt][2] = *(const uint32_t*)(xsm + AHo + o01);
        aH[kt][3] = *(const uint32_t*)(xsm + AHo + o11);
        aL[kt][0] = *(const uint32_t*)(xsm + ALo + o00);
        aL[kt][1] = *(const uint32_t*)(xsm + ALo + o10);
        aL[kt][2] = *(const uint32_t*)(xsm + ALo + o01);
        aL[kt][3] = *(const uint32_t*)(xsm + ALo + o11);
    }

    const int si0 = arow >> 6, t0 = arow & 63;
    const int si8 = (arow+8) >> 6, t8 = (arow+8) & 63;
    const int tau0 = dir ? (63 - t0) : t0;
    const int tau8 = dir ? (63 - t8) : t8;
    float* ob0 = d_xg + ((size_t)(dir*Rc + r0 + si0)*Tc + tau0)*G4c;
    float* ob8 = d_xg + ((size_t)(dir*Rc + r0 + si8)*Tc + tau8)*G4c;
    const float* bsm = (const float*)(xsm + BIAS);

    for (int nt = 0; nt < 32; ++nt){
        const int bn = nt*8 + r_q;
        float c0 = 0.f, c1 = 0.f, c2 = 0.f, c3 = 0.f;
        #pragma unroll
        for (int kt = 0; kt < KT; ++kt){
            int kc = c_q*2 + kt*16;
            uint32_t bh0 = *(const uint32_t*)(xsm + BHo + (bn*SA + kc)*2);
            uint32_t bh1 = *(const uint32_t*)(xsm + BHo + (bn*SA + kc + 8)*2);
            uint32_t bl0 = *(const uint32_t*)(xsm + BLo + (bn*SA + kc)*2);
            uint32_t bl1 = *(const uint32_t*)(xsm + BLo + (bn*SA + kc + 8)*2);
            hmma(c0,c1,c2,c3, aH[kt][0],aH[kt][1],aH[kt][2],aH[kt][3], bh0,bh1);
            hmma(c0,c1,c2,c3, aL[kt][0],aL[kt][1],aL[kt][2],aL[kt][3], bh0,bh1);
            hmma(c0,c1,c2,c3, aH[kt][0],aH[kt][1],aH[kt][2],aH[kt][3], bl0,bl1);
        }
        const int col = nt*8 + c_q*2;
        *(float2*)(ob0 + col) = make_float2(c0 + bsm[col], c1 + bsm[col+1]);
        *(float2*)(ob8 + col) = make_float2(c2 + bsm[col], c3 + bsm[col+1]);
    }
}

// --------- LSTM recurrence (f32x2, 8 seqs/block, xg prefetch) ------------
template<bool L1>
__global__ void __launch_bounds__(256) k_rec(const float* __restrict__ Whh)
{
    int dir = blockIdx.y;
    int r0  = blockIdx.x * 8;
    int k   = threadIdx.x;
    __shared__ __align__(16) float hsm[8][Hc];
    __shared__ float gsm[8][G4c];

    ull w2[32];
    const float* Wd = Whh + dir*Hc*G4c;
    #pragma unroll
    for (int i = 0; i < 32; ++i)
        w2[i] = pack2(Wd[(2*i)*G4c + k], Wd[(2*i+1)*G4c + k]);

    const int hid = k & 63, rA = k >> 6, rB = 4 + (k >> 6);
    hsm[rA][hid] = 0.f;
    hsm[rB][hid] = 0.f;
    float cc0 = 0.f, cc1 = 0.f;

    const float* xgd = d_xg + ((size_t)dir*Rc + r0)*Tc*G4c;
    float xv[8];
    #pragma unroll
    for (int rr = 0; rr < 8; ++rr)
        xv[rr] = xgd[((size_t)rr*Tc)*G4c + k];
    __syncthreads();

    for (int tau = 0; tau < Tc; ++tau){
        #pragma unroll
        for (int rr = 0; rr < 8; ++rr){
            ull a0 = 0, a1 = 0;
            const ulonglong2* hp = (const ulonglong2*)hsm[rr];
            #pragma unroll
            for (int i = 0; i < 16; ++i){
                ulonglong2 hv = hp[i];
                ffma2(a0, hv.x, w2[2*i]);
                ffma2(a1, hv.y, w2[2*i+1]);
            }
            float2 f0 = unpack2(a0), f1 = unpack2(a1);
            gsm[rr][k] = (f0.x + f1.x) + (f0.y + f1.y) + xv[rr];
        }
        const int tn = (tau+1 < Tc) ? tau+1 : tau;
        float xn[8];
        #pragma unroll
        for (int rr = 0; rr < 8; ++rr)
            xn[rr] = xgd[((size_t)rr*Tc + tn)*G4c + k];
        __syncthreads();
        {
            float gi = gsm[rA][hid],     gf = gsm[rA][64+hid];
            float gg = gsm[rA][128+hid], go = gsm[rA][192+hid];
            float cn = sigfast(gf)*cc0 + sigfast(gi)*tanhfast(gg);
            float hn = sigfast(go)*tanhfast(cn);
            cc0 = cn; hsm[rA][hid] = hn;
            if (!L1){
                size_t off = ((size_t)(dir*Rc + r0 + rA)*Tc + tau)*Hc + hid;
                __nv_bfloat16 hi, lo; bf16split(hn, hi, lo);
                d_hs0h[off] = hi; d_hs0l[off] = lo;
            }
        }
        {
            float gi = gsm[rB][hid],     gf = gsm[rB][64+hid];
            float gg = gsm[rB][128+hid], go = gsm[rB][192+hid];
            float cn = sigfast(gf)*cc1 + sigfast(gi)*tanhfast(gg);
            float hn = sigfast(go)*tanhfast(cn);
            cc1 = cn; hsm[rB][hid] = hn;
            if (!L1){
                size_t off = ((size_t)(dir*Rc + r0 + rB)*Tc + tau)*Hc + hid;
                __nv_bfloat16 hi, lo; bf16split(hn, hi, lo);
                d_hs0h[off] = hi; d_hs0l[off] = lo;
            }
        }
        #pragma unroll
        for (int rr = 0; rr < 8; ++rr) xv[rr] = xn[rr];
        __syncthreads();
    }
    if (L1){
        d_hlast[(size_t)(dir*Rc + r0 + rA)*Hc + hid] = hsm[rA][hid];
        d_hlast[(size_t)(dir*Rc + r0 + rB)*Hc + hid] = hsm[rB][hid];
    }
}

// --------------------------- final FC ------------------------------------
__global__ void __launch_bounds__(128) k_fc(const float* __restrict__ fcW,
    const float* __restrict__ fcb, float* __restrict__ out)
{
    int r = blockIdx.x * blockDim.x + threadIdx.x;
    if (r >= Rc) return;
    float acc = fcb[0];
    #pragma unroll
    for (int hh = 0; hh < Hc; ++hh) acc += d_hlast[(size_t)r*Hc + hh]        * fcW[hh];
    #pragma unroll
    for (int hh = 0; hh < Hc; ++hh) acc += d_hlast[((size_t)Rc + r)*Hc + hh] * fcW[64 + hh];
    out[r] = acc;
}

// --------------------------------------------------------------------------
extern "C" void kernel_launch(void* const* d_in, const int* in_sizes, int n_in,
                              void* d_out, int out_size)
{
    const float* x       = (const float*)d_in[0];
    const float* adj     = (const float*)d_in[1];
    const float* gat0_W  = (const float*)d_in[2];
    const float* gat0_a  = (const float*)d_in[3];
    const float* gat0_g  = (const float*)d_in[4];
    const float* gat0_b  = (const float*)d_in[5];
    const float* gat1_W  = (const float*)d_in[6];
    const float* gat1_a  = (const float*)d_in[7];
    const float* gat1_g  = (const float*)d_in[8];
    const float* gat1_b  = (const float*)d_in[9];
    const float* res_W   = (const float*)d_in[10];
    const float* res_b   = (const float*)d_in[11];
    const float* alpha   = (const float*)d_in[12];
    const float* l0_Wih  = (const float*)d_in[13];
    const float* l0_Whh  = (const float*)d_in[14];
    const float* l0_bih  = (const float*)d_in[15];
    const float* l0_bhh  = (const float*)d_in[16];
    const float* l1_Wih  = (const float*)d_in[17];
    const float* l1_Whh  = (const float*)d_in[18];
    const float* l1_bih  = (const float*)d_in[19];
    const float* l1_bhh  = (const float*)d_in[20];
    const float* fc_W    = (const float*)d_in[21];
    const float* fc_b    = (const float*)d_in[22];
    float* out = (float*)d_out;

    const int xg0_smem = 2*(128*(Hc+8)*2)    + 2*(256*(Hc+8)*2)    + 1024;   // ~112 KB
    const int xg1_smem = 2*(128*(2*Hc+8)*2)  + 2*(256*(2*Hc+8)*2)  + 1024;   // ~210 KB
    cudaFuncSetAttribute(k_attn, cudaFuncAttributeMaxDynamicSharedMemorySize, ATTN_SMEM);
    cudaFuncSetAttribute(k_xg_hmma<Hc,false>,  cudaFuncAttributeMaxDynamicSharedMemorySize, xg0_smem);
    cudaFuncSetAttribute(k_xg_hmma<2*Hc,true>, cudaFuncAttributeMaxDynamicSharedMemorySize, xg1_smem);

    // weight pre-conversion (independent -> overlap with GAT)
    k_wconv<<<(2*Hc*256 + 2*2*Hc*256 + 255)/256, 256>>>(l0_Wih, l1_Wih);

    // GAT layer 0
    k_proj<Fc, false><<<Mc*Nc/4, 256>>>(x, gat0_W, gat0_a);
    k_attn<<<dim3(Mc, 2), 256, ATTN_SMEM>>>(adj, gat0_g, gat0_b);
    // GAT layer 1
    k_proj<Hc, true><<<Mc*Nc/4, 256>>>(nullptr, gat1_W, gat1_a);
    k_attn<<<dim3(Mc, 2), 256, ATTN_SMEM>>>(adj, gat1_g, gat1_b);
    // residual combine + transpose (emits bf16 hi/lo)
    k_comb<<<Mc*Nc/4, 256>>>(x, res_W, res_b, alpha);
    // BiLSTM layer 0
    k_xg_hmma<Hc,   false><<<dim3(Rc/2, 2), 256, xg0_smem>>>(l0_bih, l0_bhh);
    k_rec<false><<<dim3(Rc/8, 2), 256>>>(l0_Whh);
    // BiLSTM layer 1
    k_xg_hmma<2*Hc, true><<<dim3(Rc/2, 2), 256, xg1_smem>>>(l1_bih, l1_bhh);
    k_rec<true><<<dim3(Rc/8, 2), 256>>>(l1_Whh);
    // final FC
    k_fc<<<(Rc + 127)/128, 128>>>(fc_W, fc_b, out);
}